// round 2
// baseline (speedup 1.0000x reference)
#include <cuda_runtime.h>
#include <math.h>

#define BS     4
#define NQ     10000
#define NV     13294
#define EMBED  256
#define HEADS  8
#define DH     32
#define LEVELS 4
#define POINTS 4

// scratch (no allocations allowed)
__device__ float g_v[BS * NV * EMBED];                       // projected value  [b, pos, h*32+d]
__device__ float g_proj_off[BS * NQ * 256];                  // offsets (h,l,p,xy) per query
__device__ float g_proj_w[BS * NQ * 128];                    // attn logits (h, l*4+p) per query
__device__ float g_msda[BS * NQ * EMBED];                    // sampled output before Wo

// ---------------------------------------------------------------------------
// Tiled fp32 GEMM: C[M,N] = A[M,K] @ B[K,N] + bias[N] (+ R[M,N] if ADD_RESID)
// BM=BN=64, BK=16, 256 threads, 4x4 per thread. N must be a multiple of 64.
// ---------------------------------------------------------------------------
template <int ADD_RESID>
__global__ void gemm64(const float* __restrict__ A, const float* __restrict__ B,
                       const float* __restrict__ bias, const float* __restrict__ R,
                       float* __restrict__ C, int M, int N, int K)
{
    __shared__ float As[16][65];   // [k][m], padded
    __shared__ float Bs[16][64];   // [k][n]
    const int tid = threadIdx.x;
    const int bm = blockIdx.y * 64, bn = blockIdx.x * 64;
    const int tx = tid & 15, ty = tid >> 4;

    float acc[4][4] = {};

    for (int k0 = 0; k0 < K; k0 += 16) {
#pragma unroll
        for (int t = 0; t < 4; t++) {                 // A tile: 64x16
            int i  = tid + t * 256;
            int kl = i & 15, ml = i >> 4;
            int m  = bm + ml;
            As[kl][ml] = (m < M) ? A[(size_t)m * K + k0 + kl] : 0.f;
        }
#pragma unroll
        for (int t = 0; t < 4; t++) {                 // B tile: 16x64
            int i  = tid + t * 256;
            int nl = i & 63, kl = i >> 6;
            Bs[kl][nl] = B[(size_t)(k0 + kl) * N + bn + nl];
        }
        __syncthreads();
#pragma unroll
        for (int kl = 0; kl < 16; kl++) {
            float a[4], b[4];
#pragma unroll
            for (int i = 0; i < 4; i++) a[i] = As[kl][ty * 4 + i];
#pragma unroll
            for (int j = 0; j < 4; j++) b[j] = Bs[kl][tx * 4 + j];
#pragma unroll
            for (int i = 0; i < 4; i++)
#pragma unroll
                for (int j = 0; j < 4; j++)
                    acc[i][j] += a[i] * b[j];
        }
        __syncthreads();
    }

#pragma unroll
    for (int i = 0; i < 4; i++) {
        int m = bm + ty * 4 + i;
        if (m >= M) continue;
#pragma unroll
        for (int j = 0; j < 4; j++) {
            int n = bn + tx * 4 + j;
            float o = acc[i][j] + bias[n];
            if (ADD_RESID) o += R[(size_t)m * N + n];
            C[(size_t)m * N + n] = o;
        }
    }
}

// ---------------------------------------------------------------------------
// Deformable sampling: one block (256 thr) per query; warp = head, lane = dim.
// ---------------------------------------------------------------------------
__global__ void msda_kernel(const float* __restrict__ refp)  // [bs, nq, 4, 2]
{
    const int bq  = blockIdx.x;            // b*NQ + q
    const int b   = bq / NQ;
    const int tid = threadIdx.x;
    const int h   = tid >> 5, d = tid & 31;

    __shared__ float s_off[256];
    __shared__ float s_w[128];
    __shared__ float s_ref[8];

    s_off[tid] = g_proj_off[(size_t)bq * 256 + tid];
    if (tid < 128) s_w[tid] = g_proj_w[(size_t)bq * 128 + tid];
    if (tid < 8)   s_ref[tid] = refp[(size_t)bq * 8 + tid];
    __syncthreads();

    // softmax over the 16 (level,point) logits of this head
    float mx = -1e30f;
#pragma unroll
    for (int i = 0; i < 16; i++) mx = fmaxf(mx, s_w[h * 16 + i]);
    float ssum = 0.f;
#pragma unroll
    for (int i = 0; i < 16; i++) ssum += __expf(s_w[h * 16 + i] - mx);
    const float inv = 1.f / ssum;

    const int   Hs[4]     = {100, 50, 25, 13};
    const int   starts[4] = {0, 10000, 12500, 13125};
    const float* vb = g_v + (size_t)b * NV * EMBED + h * DH + d;

    float acc = 0.f;
#pragma unroll
    for (int l = 0; l < 4; l++) {
        const int   H = Hs[l], W = Hs[l];
        const float rx = s_ref[l * 2 + 0], ry = s_ref[l * 2 + 1];
        const float invW = 1.f / (float)W, invH = 1.f / (float)H;
#pragma unroll
        for (int p = 0; p < 4; p++) {
            const int oi = ((h * 4 + l) * 4 + p) * 2;
            const float x = (rx + s_off[oi]     * invW) * (float)W - 0.5f;
            const float y = (ry + s_off[oi + 1] * invH) * (float)H - 0.5f;
            const float x0f = floorf(x), y0f = floorf(y);
            const float fx = x - x0f, fy = y - y0f;
            const int x0 = (int)x0f, y0 = (int)y0f;
            const float a = __expf(s_w[h * 16 + l * 4 + p] - mx) * inv;

            float s = 0.f;
#pragma unroll
            for (int dy = 0; dy < 2; dy++) {
                const int yi = y0 + dy;
                if (yi < 0 || yi >= H) continue;
                const float wy = dy ? fy : 1.f - fy;
#pragma unroll
                for (int dx = 0; dx < 2; dx++) {
                    const int xi = x0 + dx;
                    if (xi < 0 || xi >= W) continue;
                    const float wx = dx ? fx : 1.f - fx;
                    const int idx = starts[l] + yi * W + xi;
                    s += wx * wy * vb[(size_t)idx * EMBED];
                }
            }
            acc += a * s;
        }
    }
    g_msda[(size_t)bq * 256 + tid] = acc;
}

// ---------------------------------------------------------------------------
extern "C" void kernel_launch(void* const* d_in, const int* in_sizes, int n_in,
                              void* d_out, int out_size)
{
    const float* query = (const float*)d_in[0];   // [4,10000,256]
    const float* value = (const float*)d_in[1];   // [4,13294,256]
    const float* refp  = (const float*)d_in[2];   // [4,10000,4,2]
    // d_in[3]: spatial_shapes (hardcoded)
    const float* Wv   = (const float*)d_in[4];
    const float* bv   = (const float*)d_in[5];
    const float* Woff = (const float*)d_in[6];
    const float* boff = (const float*)d_in[7];
    const float* Ww   = (const float*)d_in[8];
    const float* bw   = (const float*)d_in[9];
    const float* Wo   = (const float*)d_in[10];
    const float* bo   = (const float*)d_in[11];
    float* out = (float*)d_out;

    float *p_v, *p_poff, *p_pw, *p_msda;
    cudaGetSymbolAddress((void**)&p_v,    g_v);
    cudaGetSymbolAddress((void**)&p_poff, g_proj_off);
    cudaGetSymbolAddress((void**)&p_pw,   g_proj_w);
    cudaGetSymbolAddress((void**)&p_msda, g_msda);

    const int Mv = BS * NV;   // 53176
    const int Mq = BS * NQ;   // 40000

    // 1) v = value @ Wv + bv
    gemm64<0><<<dim3(256 / 64, (Mv + 63) / 64), 256>>>(value, Wv, bv, nullptr, p_v, Mv, 256, 256);
    // 2) offsets = query @ Woff + boff
    gemm64<0><<<dim3(256 / 64, (Mq + 63) / 64), 256>>>(query, Woff, boff, nullptr, p_poff, Mq, 256, 256);
    // 3) logits = query @ Ww + bw
    gemm64<0><<<dim3(128 / 64, (Mq + 63) / 64), 256>>>(query, Ww, bw, nullptr, p_pw, Mq, 128, 256);
    // 4) deformable sampling
    msda_kernel<<<Mq, 256>>>(refp);
    // 5) out = msda @ Wo + bo + query
    gemm64<1><<<dim3(256 / 64, (Mq + 63) / 64), 256>>>(p_msda, Wo, bo, query, out, Mq, 256, 256);
}

// round 3
// speedup vs baseline: 1.3284x; 1.3284x over previous
#include <cuda_runtime.h>
#include <cuda_bf16.h>
#include <math.h>

#define BS     4
#define NQ     10000
#define NV     13294
#define EMBED  256
#define HEADS  8
#define DH     32

// scratch (no allocations allowed)
__device__ __nv_bfloat16 g_vh[BS * NV * EMBED];   // projected value, bf16
__device__ float g_proj_off[BS * NQ * 256];
__device__ float g_proj_w[BS * NQ * 128];
__device__ float g_msda[BS * NQ * 256];

// ---------------------------------------------------------------------------
// 128x128 tiled fp32 GEMM, BK=16, 256 threads, 8x8 per thread.
// C = A[M,K] @ B[K,N] + bias[N] (+ R if ADD_RESID). Output fp32 or bf16.
// N must be a multiple of 128.
// ---------------------------------------------------------------------------
template <int ADD_RESID, int OUT_BF16>
__global__ void __launch_bounds__(256, 2)
gemm128(const float* __restrict__ A, const float* __restrict__ B,
        const float* __restrict__ bias, const float* __restrict__ R,
        void* __restrict__ Cv, int M, int N, int K)
{
    __shared__ float As[16][132];   // [k][m], padded (132 % 4 == 0 for float4)
    __shared__ float Bs[16][128];   // [k][n]
    const int tid = threadIdx.x;
    const int bm = blockIdx.y * 128, bn = blockIdx.x * 128;
    const int tx = tid & 15, ty = tid >> 4;

    const int am  = tid >> 1;           // 0..127 (A row within tile)
    const int ak  = (tid & 1) * 8;      // 0 or 8 (A k-offset)
    const int bk  = tid >> 4;           // 0..15 (B row within tile)
    const int bnn = (tid & 15) * 8;     // B col offset

    float acc[8][8] = {};

    for (int k0 = 0; k0 < K; k0 += 16) {
        { // A tile 128x16, transposed into As[k][m]
            int m = bm + am;
            float4 a0, a1;
            if (m < M) {
                const float4* ap = (const float4*)(A + (size_t)m * K + k0 + ak);
                a0 = ap[0]; a1 = ap[1];
            } else {
                a0 = make_float4(0.f, 0.f, 0.f, 0.f); a1 = a0;
            }
            As[ak + 0][am] = a0.x; As[ak + 1][am] = a0.y;
            As[ak + 2][am] = a0.z; As[ak + 3][am] = a0.w;
            As[ak + 4][am] = a1.x; As[ak + 5][am] = a1.y;
            As[ak + 6][am] = a1.z; As[ak + 7][am] = a1.w;
        }
        { // B tile 16x128
            const float4* bp = (const float4*)(B + (size_t)(k0 + bk) * N + bn + bnn);
            *(float4*)&Bs[bk][bnn]     = bp[0];
            *(float4*)&Bs[bk][bnn + 4] = bp[1];
        }
        __syncthreads();
#pragma unroll
        for (int kl = 0; kl < 16; kl++) {
            float a[8], b[8];
            *(float4*)&a[0] = *(const float4*)&As[kl][ty * 8];
            *(float4*)&a[4] = *(const float4*)&As[kl][ty * 8 + 4];
            *(float4*)&b[0] = *(const float4*)&Bs[kl][tx * 8];
            *(float4*)&b[4] = *(const float4*)&Bs[kl][tx * 8 + 4];
#pragma unroll
            for (int i = 0; i < 8; i++)
#pragma unroll
                for (int j = 0; j < 8; j++)
                    acc[i][j] += a[i] * b[j];
        }
        __syncthreads();
    }

    // epilogue
    float bsv[8];
#pragma unroll
    for (int j = 0; j < 8; j++) bsv[j] = bias[bn + tx * 8 + j];

#pragma unroll
    for (int i = 0; i < 8; i++) {
        int m = bm + ty * 8 + i;
        if (m >= M) continue;
        float o[8];
#pragma unroll
        for (int j = 0; j < 8; j++) o[j] = acc[i][j] + bsv[j];
        if (ADD_RESID) {
            const float4* rp = (const float4*)(R + (size_t)m * N + bn + tx * 8);
            float4 r0 = rp[0], r1 = rp[1];
            o[0] += r0.x; o[1] += r0.y; o[2] += r0.z; o[3] += r0.w;
            o[4] += r1.x; o[5] += r1.y; o[6] += r1.z; o[7] += r1.w;
        }
        if (OUT_BF16) {
            __nv_bfloat162* cp =
                (__nv_bfloat162*)((__nv_bfloat16*)Cv + (size_t)m * N + bn + tx * 8);
#pragma unroll
            for (int j = 0; j < 4; j++)
                cp[j] = __floats2bfloat162_rn(o[2 * j], o[2 * j + 1]);
        } else {
            float* C = (float*)Cv + (size_t)m * N + bn + tx * 8;
            *(float4*)C       = make_float4(o[0], o[1], o[2], o[3]);
            *(float4*)(C + 4) = make_float4(o[4], o[5], o[6], o[7]);
        }
    }
}

// ---------------------------------------------------------------------------
// Deformable sampling, two-phase.
// Phase 1 (128 thr): one thread per (head, level, point) -> softmax weight,
//   4 clamped gather indices, 4 fused (bilinear * attention) weights -> smem.
// Phase 2 (256 thr): warp = head, lane = channel; pure gather + FMA.
// ---------------------------------------------------------------------------
__global__ void msda_kernel(const float* __restrict__ refp)  // [bs, nq, 4, 2]
{
    const int bq  = blockIdx.x;
    const int b   = bq / NQ;
    const int tid = threadIdx.x;

    __shared__ int   s_idx[512];   // [h*16+lp][corner] element offsets (pos<<8)
    __shared__ float s_wt[512];    // fused weights

    if (tid < 128) {
        const int h = tid >> 4, lp = tid & 15, l = lp >> 2;

        // softmax over this head's 16 logits (16-lane shfl groups, warps 0-3 full)
        float logit = g_proj_w[(size_t)bq * 128 + tid];
        float mx = logit;
#pragma unroll
        for (int o = 8; o; o >>= 1) mx = fmaxf(mx, __shfl_xor_sync(0xffffffffu, mx, o));
        float e = __expf(logit - mx);
        float ssum = e;
#pragma unroll
        for (int o = 8; o; o >>= 1) ssum += __shfl_xor_sync(0xffffffffu, ssum, o);
        const float a = e / ssum;

        const int HWs[4]    = {100, 50, 25, 13};
        const int starts[4] = {0, 10000, 12500, 13125};
        const int W = HWs[l], H = W, st = starts[l];

        // loc*W - 0.5 = ref*W + off - 0.5  (normalizer cancels)
        const float2 off = *(const float2*)(g_proj_off + (size_t)bq * 256 + tid * 2);
        const float2 ref = *(const float2*)(refp + (size_t)bq * 8 + l * 2);
        const float x = ref.x * (float)W + off.x - 0.5f;
        const float y = ref.y * (float)H + off.y - 0.5f;
        const float x0f = floorf(x), y0f = floorf(y);
        const float fx = x - x0f, fy = y - y0f;
        const int x0 = (int)x0f, y0 = (int)y0f;
        const int x1 = x0 + 1,  y1 = y0 + 1;

        const bool vx0 = (x0 >= 0) & (x0 < W), vx1 = (x1 >= 0) & (x1 < W);
        const bool vy0 = (y0 >= 0) & (y0 < H), vy1 = (y1 >= 0) & (y1 < H);
        const int cx0 = min(max(x0, 0), W - 1), cx1 = min(max(x1, 0), W - 1);
        const int cy0 = min(max(y0, 0), H - 1), cy1 = min(max(y1, 0), H - 1);

        const int base = tid * 4;
        s_idx[base + 0] = (st + cy0 * W + cx0) << 8;
        s_idx[base + 1] = (st + cy0 * W + cx1) << 8;
        s_idx[base + 2] = (st + cy1 * W + cx0) << 8;
        s_idx[base + 3] = (st + cy1 * W + cx1) << 8;
        s_wt[base + 0] = (vx0 && vy0) ? (1.f - fx) * (1.f - fy) * a : 0.f;
        s_wt[base + 1] = (vx1 && vy0) ? fx * (1.f - fy) * a : 0.f;
        s_wt[base + 2] = (vx0 && vy1) ? (1.f - fx) * fy * a : 0.f;
        s_wt[base + 3] = (vx1 && vy1) ? fx * fy * a : 0.f;
    }
    __syncthreads();

    const int h = tid >> 5, d = tid & 31;
    const __nv_bfloat16* vb = g_vh + (size_t)b * NV * EMBED + h * DH + d;

    float acc = 0.f;
#pragma unroll
    for (int lp = 0; lp < 16; lp++) {
        const int base = (h * 16 + lp) * 4;
        const int4   ix = *(const int4*)&s_idx[base];
        const float4 w  = *(const float4*)&s_wt[base];
        acc += w.x * __bfloat162float(vb[ix.x]);
        acc += w.y * __bfloat162float(vb[ix.y]);
        acc += w.z * __bfloat162float(vb[ix.z]);
        acc += w.w * __bfloat162float(vb[ix.w]);
    }
    g_msda[(size_t)bq * 256 + tid] = acc;
}

// ---------------------------------------------------------------------------
extern "C" void kernel_launch(void* const* d_in, const int* in_sizes, int n_in,
                              void* d_out, int out_size)
{
    const float* query = (const float*)d_in[0];
    const float* value = (const float*)d_in[1];
    const float* refp  = (const float*)d_in[2];
    const float* Wv    = (const float*)d_in[4];
    const float* bv    = (const float*)d_in[5];
    const float* Woff  = (const float*)d_in[6];
    const float* boff  = (const float*)d_in[7];
    const float* Ww    = (const float*)d_in[8];
    const float* bw    = (const float*)d_in[9];
    const float* Wo    = (const float*)d_in[10];
    const float* bo    = (const float*)d_in[11];
    float* out = (float*)d_out;

    void *p_vh; float *p_poff, *p_pw, *p_msda;
    cudaGetSymbolAddress(&p_vh, g_vh);
    cudaGetSymbolAddress((void**)&p_poff, g_proj_off);
    cudaGetSymbolAddress((void**)&p_pw,   g_proj_w);
    cudaGetSymbolAddress((void**)&p_msda, g_msda);

    const int Mv = BS * NV;   // 53176
    const int Mq = BS * NQ;   // 40000

    // 1) v = bf16(value @ Wv + bv)
    gemm128<0, 1><<<dim3(256 / 128, (Mv + 127) / 128), 256>>>(
        value, Wv, bv, nullptr, p_vh, Mv, 256, 256);
    // 2) offsets = query @ Woff + boff
    gemm128<0, 0><<<dim3(256 / 128, (Mq + 127) / 128), 256>>>(
        query, Woff, boff, nullptr, p_poff, Mq, 256, 256);
    // 3) logits = query @ Ww + bw
    gemm128<0, 0><<<dim3(128 / 128, (Mq + 127) / 128), 256>>>(
        query, Ww, bw, nullptr, p_pw, Mq, 128, 256);
    // 4) deformable sampling
    msda_kernel<<<Mq, 256>>>(refp);
    // 5) out = msda @ Wo + bo + query
    gemm128<1, 0><<<dim3(256 / 128, (Mq + 127) / 128), 256>>>(
        p_msda, Wo, bo, query, out, Mq, 256, 256);
}

// round 4
// speedup vs baseline: 2.3413x; 1.7625x over previous
#include <cuda_runtime.h>
#include <cuda_bf16.h>
#include <math.h>
#include <stdint.h>

#define BS     4
#define NQ     10000
#define NV     13294
#define EMBED  256
#define HEADS  8
#define DH     32

// scratch (no allocations allowed)
__device__ __nv_bfloat16 g_vh[BS * NV * EMBED];   // projected value, bf16
__device__ float g_proj_off[BS * NQ * 256];
__device__ float g_proj_w[BS * NQ * 128];
__device__ float g_msda[BS * NQ * 256];

// ---------------------------------------------------------------------------
// tf32 tensor-core GEMM: C = A[M,K] @ B[K,N] + bias (+R). 128x128 tile, BK=16,
// 256 threads (8 warps as 2x4), warp tile 64x32 = 4x4 m16n8k8 mma tiles.
// N must be a multiple of 128, K a multiple of 16.
// ---------------------------------------------------------------------------
template <int ADD_RESID, int OUT_BF16>
__global__ void __launch_bounds__(256, 2)
gemm_tc(const float* __restrict__ A, const float* __restrict__ B,
        const float* __restrict__ bias, const float* __restrict__ R,
        void* __restrict__ Cv, int M, int N, int K)
{
    __shared__ uint32_t As[128 * 20];   // [m][k], pad 20 -> conflict-free frags
    __shared__ uint32_t Bs[16 * 136];   // [k][n], pad 136 -> conflict-free frags

    const int tid  = threadIdx.x;
    const int lane = tid & 31;
    const int wid  = tid >> 5;
    const int wm   = (wid >> 2) * 64;   // 0 / 64
    const int wn   = (wid & 3) * 32;    // 0..96
    const int bm   = blockIdx.y * 128, bn = blockIdx.x * 128;
    const int lq   = lane >> 2, lr = lane & 3;

    const int am = tid >> 1, ak = (tid & 1) * 8;      // A: 128 rows x 16 k
    const int bk = tid >> 4, bn8 = (tid & 15) * 8;    // B: 16 rows x 128 n

    float acc[4][4][4] = {};   // [im][in][creg]

    for (int k0 = 0; k0 < K; k0 += 16) {
        { // A tile -> smem (tf32)
            int m = bm + am;
            float v[8];
            if (m < M) {
                const float4* ap = (const float4*)(A + (size_t)m * K + k0 + ak);
                float4 x = ap[0], y = ap[1];
                v[0]=x.x; v[1]=x.y; v[2]=x.z; v[3]=x.w;
                v[4]=y.x; v[5]=y.y; v[6]=y.z; v[7]=y.w;
            } else {
#pragma unroll
                for (int i = 0; i < 8; i++) v[i] = 0.f;
            }
#pragma unroll
            for (int i = 0; i < 8; i++) {
                uint32_t t; asm("cvt.rna.tf32.f32 %0, %1;" : "=r"(t) : "f"(v[i]));
                As[am * 20 + ak + i] = t;
            }
        }
        { // B tile -> smem (tf32)
            const float4* bp = (const float4*)(B + (size_t)(k0 + bk) * N + bn + bn8);
            float4 x = bp[0], y = bp[1];
            float v[8] = {x.x, x.y, x.z, x.w, y.x, y.y, y.z, y.w};
#pragma unroll
            for (int i = 0; i < 8; i++) {
                uint32_t t; asm("cvt.rna.tf32.f32 %0, %1;" : "=r"(t) : "f"(v[i]));
                Bs[bk * 136 + bn8 + i] = t;
            }
        }
        __syncthreads();

#pragma unroll
        for (int ks = 0; ks < 16; ks += 8) {
            uint32_t af[4][4], bf[4][2];
#pragma unroll
            for (int im = 0; im < 4; im++) {
                int m0 = wm + im * 16 + lq;
                af[im][0] = As[m0 * 20 + ks + lr];
                af[im][1] = As[(m0 + 8) * 20 + ks + lr];
                af[im][2] = As[m0 * 20 + ks + 4 + lr];
                af[im][3] = As[(m0 + 8) * 20 + ks + 4 + lr];
            }
#pragma unroll
            for (int in = 0; in < 4; in++) {
                int n0 = wn + in * 8 + lq;
                bf[in][0] = Bs[(ks + lr) * 136 + n0];
                bf[in][1] = Bs[(ks + 4 + lr) * 136 + n0];
            }
#pragma unroll
            for (int im = 0; im < 4; im++)
#pragma unroll
                for (int in = 0; in < 4; in++) {
                    asm volatile(
                        "mma.sync.aligned.m16n8k8.row.col.f32.tf32.tf32.f32 "
                        "{%0,%1,%2,%3}, {%4,%5,%6,%7}, {%8,%9}, {%0,%1,%2,%3};"
                        : "+f"(acc[im][in][0]), "+f"(acc[im][in][1]),
                          "+f"(acc[im][in][2]), "+f"(acc[im][in][3])
                        : "r"(af[im][0]), "r"(af[im][1]),
                          "r"(af[im][2]), "r"(af[im][3]),
                          "r"(bf[in][0]), "r"(bf[in][1]));
                }
        }
        __syncthreads();
    }

    // epilogue: c0,c1 -> (row lq, cols 2lr,2lr+1); c2,c3 -> row lq+8
#pragma unroll
    for (int im = 0; im < 4; im++) {
#pragma unroll
        for (int half = 0; half < 2; half++) {
            int m = bm + wm + im * 16 + lq + half * 8;
            if (m >= M) continue;
#pragma unroll
            for (int in = 0; in < 4; in++) {
                int n = bn + wn + in * 8 + lr * 2;
                float o0 = acc[im][in][half * 2 + 0] + bias[n];
                float o1 = acc[im][in][half * 2 + 1] + bias[n + 1];
                if (ADD_RESID) {
                    const float2 r = *(const float2*)(R + (size_t)m * N + n);
                    o0 += r.x; o1 += r.y;
                }
                if (OUT_BF16) {
                    *(__nv_bfloat162*)((__nv_bfloat16*)Cv + (size_t)m * N + n) =
                        __floats2bfloat162_rn(o0, o1);
                } else {
                    *(float2*)((float*)Cv + (size_t)m * N + n) = make_float2(o0, o1);
                }
            }
        }
    }
}

// ---------------------------------------------------------------------------
// Deformable sampling, two-phase.
// Phase 1 (128 thr): per (head,level,point): softmax, 4 indices + fused weights.
// Phase 2: warp = head; 16 lanes x bf16x2 cover 32 channels; the two half-warps
// process even/odd (level,point) slots in the same LDG -> half the L1 requests.
// ---------------------------------------------------------------------------
__global__ void msda_kernel(const float* __restrict__ refp)  // [bs, nq, 4, 2]
{
    const int bq  = blockIdx.x;
    const int b   = bq / NQ;
    const int tid = threadIdx.x;

    __shared__ int   s_idx[512];   // [h*16+lp][corner], pos in bf16x2 units (pos*128)
    __shared__ float s_wt[512];    // fused bilinear*attention weights

    if (tid < 128) {
        const int h = tid >> 4, lp = tid & 15, l = lp >> 2;
        (void)h;

        // softmax over this head's 16 logits (16-lane shfl groups)
        float logit = g_proj_w[(size_t)bq * 128 + tid];
        float mx = logit;
#pragma unroll
        for (int o = 8; o; o >>= 1) mx = fmaxf(mx, __shfl_xor_sync(0xffffffffu, mx, o));
        float e = __expf(logit - mx);
        float ssum = e;
#pragma unroll
        for (int o = 8; o; o >>= 1) ssum += __shfl_xor_sync(0xffffffffu, ssum, o);
        const float a = e / ssum;

        const int HWs[4]    = {100, 50, 25, 13};
        const int starts[4] = {0, 10000, 12500, 13125};
        const int W = HWs[l], H = W, st = starts[l];

        const float2 off = *(const float2*)(g_proj_off + (size_t)bq * 256 + tid * 2);
        const float2 ref = *(const float2*)(refp + (size_t)bq * 8 + l * 2);
        const float x = ref.x * (float)W + off.x - 0.5f;
        const float y = ref.y * (float)H + off.y - 0.5f;
        const float x0f = floorf(x), y0f = floorf(y);
        const float fx = x - x0f, fy = y - y0f;
        const int x0 = (int)x0f, y0 = (int)y0f;
        const int x1 = x0 + 1,  y1 = y0 + 1;

        const bool vx0 = (x0 >= 0) & (x0 < W), vx1 = (x1 >= 0) & (x1 < W);
        const bool vy0 = (y0 >= 0) & (y0 < H), vy1 = (y1 >= 0) & (y1 < H);
        const int cx0 = min(max(x0, 0), W - 1), cx1 = min(max(x1, 0), W - 1);
        const int cy0 = min(max(y0, 0), H - 1), cy1 = min(max(y1, 0), H - 1);

        const int base = tid * 4;
        s_idx[base + 0] = (st + cy0 * W + cx0) * 128;
        s_idx[base + 1] = (st + cy0 * W + cx1) * 128;
        s_idx[base + 2] = (st + cy1 * W + cx0) * 128;
        s_idx[base + 3] = (st + cy1 * W + cx1) * 128;
        s_wt[base + 0] = (vx0 && vy0) ? (1.f - fx) * (1.f - fy) * a : 0.f;
        s_wt[base + 1] = (vx1 && vy0) ? fx * (1.f - fy) * a : 0.f;
        s_wt[base + 2] = (vx0 && vy1) ? (1.f - fx) * fy * a : 0.f;
        s_wt[base + 3] = (vx1 && vy1) ? fx * fy * a : 0.f;
    }
    __syncthreads();

    const int h    = tid >> 5, lane = tid & 31;
    const int half = lane >> 4, dd = lane & 15;      // dd: bf16x2 channel pair
    const __nv_bfloat162* vb =
        (const __nv_bfloat162*)(g_vh + (size_t)b * NV * EMBED + h * DH) + dd;

    float2 acc = make_float2(0.f, 0.f);
#pragma unroll
    for (int lp2 = 0; lp2 < 8; lp2++) {
        const int lp   = lp2 * 2 + half;
        const int base = (h * 16 + lp) * 4;
        const int4   ix = *(const int4*)&s_idx[base];
        const float4 w  = *(const float4*)&s_wt[base];
        float2 v0 = __bfloat1622float2(vb[ix.x]);
        float2 v1 = __bfloat1622float2(vb[ix.y]);
        float2 v2 = __bfloat1622float2(vb[ix.z]);
        float2 v3 = __bfloat1622float2(vb[ix.w]);
        acc.x += w.x * v0.x + w.y * v1.x + w.z * v2.x + w.w * v3.x;
        acc.y += w.x * v0.y + w.y * v1.y + w.z * v2.y + w.w * v3.y;
    }
    // combine even/odd halves
    acc.x += __shfl_xor_sync(0xffffffffu, acc.x, 16);
    acc.y += __shfl_xor_sync(0xffffffffu, acc.y, 16);
    if (half == 0)
        ((float2*)(g_msda + (size_t)bq * 256 + h * DH))[dd] = acc;
}

// ---------------------------------------------------------------------------
extern "C" void kernel_launch(void* const* d_in, const int* in_sizes, int n_in,
                              void* d_out, int out_size)
{
    const float* query = (const float*)d_in[0];
    const float* value = (const float*)d_in[1];
    const float* refp  = (const float*)d_in[2];
    const float* Wv    = (const float*)d_in[4];
    const float* bv    = (const float*)d_in[5];
    const float* Woff  = (const float*)d_in[6];
    const float* boff  = (const float*)d_in[7];
    const float* Ww    = (const float*)d_in[8];
    const float* bw    = (const float*)d_in[9];
    const float* Wo    = (const float*)d_in[10];
    const float* bo    = (const float*)d_in[11];
    float* out = (float*)d_out;

    void *p_vh; float *p_poff, *p_pw, *p_msda;
    cudaGetSymbolAddress(&p_vh, g_vh);
    cudaGetSymbolAddress((void**)&p_poff, g_proj_off);
    cudaGetSymbolAddress((void**)&p_pw,   g_proj_w);
    cudaGetSymbolAddress((void**)&p_msda, g_msda);

    const int Mv = BS * NV;   // 53176
    const int Mq = BS * NQ;   // 40000

    // 1) v = bf16(value @ Wv + bv)
    gemm_tc<0, 1><<<dim3(2, (Mv + 127) / 128), 256>>>(value, Wv, bv, nullptr, p_vh, Mv, 256, 256);
    // 2) offsets = query @ Woff + boff
    gemm_tc<0, 0><<<dim3(2, (Mq + 127) / 128), 256>>>(query, Woff, boff, nullptr, p_poff, Mq, 256, 256);
    // 3) logits = query @ Ww + bw
    gemm_tc<0, 0><<<dim3(1, (Mq + 127) / 128), 256>>>(query, Ww, bw, nullptr, p_pw, Mq, 128, 256);
    // 4) deformable sampling
    msda_kernel<<<Mq, 256>>>(refp);
    // 5) out = msda @ Wo + bo + query
    gemm_tc<1, 0><<<dim3(2, (Mq + 127) / 128), 256>>>(p_msda, Wo, bo, query, out, Mq, 256, 256);
}

// round 8
// speedup vs baseline: 3.0602x; 1.3071x over previous
#include <cuda_runtime.h>
#include <cuda_bf16.h>
#include <math.h>
#include <stdint.h>

#define BS     4
#define NQ     10000
#define NV     13294
#define EMBED  256
#define HEADS  8
#define DH     32

// scratch (no allocations allowed)
__device__ __nv_bfloat16 g_vh[BS * NV * EMBED];   // projected value, bf16
__device__ float g_proj_off[BS * NQ * 256];
__device__ float g_proj_w[BS * NQ * 128];
__device__ float g_msda[BS * NQ * 256];

// ---------------------------------------------------------------------------
// bf16 tensor-core GEMM: C = A[M,K] @ B[K,N] + bias (+R). 128x128 tile, BK=16,
// 256 threads (8 warps as 2x4), warp tile 64x32 = 4x4 m16n8k16 mma tiles.
// Fragments via ldmatrix (A: x4, B: x4.trans), conflict-free padded smem.
// N multiple of 128, K multiple of 16.
// ---------------------------------------------------------------------------
template <int ADD_RESID, int OUT_BF16>
__global__ void __launch_bounds__(256, 2)
gemm_tc(const float* __restrict__ A, const float* __restrict__ B,
        const float* __restrict__ bias, const float* __restrict__ R,
        void* __restrict__ Cv, int M, int N, int K)
{
    __shared__ __align__(16) __nv_bfloat16 As[128 * 24];  // [m][k], row stride 24 halves
    __shared__ __align__(16) __nv_bfloat16 Bs[16 * 136];  // [k][n], row stride 136 halves

    const int tid  = threadIdx.x;
    const int lane = tid & 31;
    const int wid  = tid >> 5;
    const int wm   = (wid >> 2) * 64;   // 0 / 64
    const int wn   = (wid & 3) * 32;    // 0..96
    const int bm   = blockIdx.y * 128, bn = blockIdx.x * 128;
    const int lq   = lane >> 2, lr = lane & 3;

    const int am = tid >> 1, ak = (tid & 1) * 8;      // A: 128 rows x 16 k
    const int bk = tid >> 4, bn8 = (tid & 15) * 8;    // B: 16 rows x 128 n

    const uint32_t a_smem = (uint32_t)__cvta_generic_to_shared(As);
    const uint32_t b_smem = (uint32_t)__cvta_generic_to_shared(Bs);

    float acc[4][4][4] = {};   // [im][in][creg]

    for (int k0 = 0; k0 < K; k0 += 16) {
        { // A tile -> smem bf16
            int m = bm + am;
            float4 x, y;
            if (m < M) {
                const float4* ap = (const float4*)(A + (size_t)m * K + k0 + ak);
                x = ap[0]; y = ap[1];
            } else {
                x = make_float4(0.f, 0.f, 0.f, 0.f); y = x;
            }
            __nv_bfloat162 h0 = __floats2bfloat162_rn(x.x, x.y);
            __nv_bfloat162 h1 = __floats2bfloat162_rn(x.z, x.w);
            __nv_bfloat162 h2 = __floats2bfloat162_rn(y.x, y.y);
            __nv_bfloat162 h3 = __floats2bfloat162_rn(y.z, y.w);
            uint32_t u0, u1, u2, u3;
            memcpy(&u0, &h0, 4); memcpy(&u1, &h1, 4);
            memcpy(&u2, &h2, 4); memcpy(&u3, &h3, 4);
            *(uint4*)&As[am * 24 + ak] = make_uint4(u0, u1, u2, u3);
        }
        { // B tile -> smem bf16
            const float4* bp = (const float4*)(B + (size_t)(k0 + bk) * N + bn + bn8);
            float4 x = bp[0], y = bp[1];
            __nv_bfloat162 h0 = __floats2bfloat162_rn(x.x, x.y);
            __nv_bfloat162 h1 = __floats2bfloat162_rn(x.z, x.w);
            __nv_bfloat162 h2 = __floats2bfloat162_rn(y.x, y.y);
            __nv_bfloat162 h3 = __floats2bfloat162_rn(y.z, y.w);
            uint32_t u0, u1, u2, u3;
            memcpy(&u0, &h0, 4); memcpy(&u1, &h1, 4);
            memcpy(&u2, &h2, 4); memcpy(&u3, &h3, 4);
            *(uint4*)&Bs[bk * 136 + bn8] = make_uint4(u0, u1, u2, u3);
        }
        __syncthreads();

        uint32_t af[4][4], bfr[2][4];
#pragma unroll
        for (int im = 0; im < 4; im++) {
            uint32_t addr = a_smem +
                ((wm + im * 16 + (lane & 15)) * 24 + (lane >> 4) * 8) * 2;
            asm volatile("ldmatrix.sync.aligned.m8n8.x4.shared.b16 {%0,%1,%2,%3}, [%4];"
                         : "=r"(af[im][0]), "=r"(af[im][1]),
                           "=r"(af[im][2]), "=r"(af[im][3]) : "r"(addr));
        }
#pragma unroll
        for (int in2 = 0; in2 < 2; in2++) {
            uint32_t addr = b_smem +
                ((lane & 15) * 136 + wn + in2 * 16 + (lane >> 4) * 8) * 2;
            asm volatile("ldmatrix.sync.aligned.m8n8.x4.trans.shared.b16 {%0,%1,%2,%3}, [%4];"
                         : "=r"(bfr[in2][0]), "=r"(bfr[in2][1]),
                           "=r"(bfr[in2][2]), "=r"(bfr[in2][3]) : "r"(addr));
        }
#pragma unroll
        for (int im = 0; im < 4; im++)
#pragma unroll
            for (int in = 0; in < 4; in++) {
                asm volatile(
                    "mma.sync.aligned.m16n8k16.row.col.f32.bf16.bf16.f32 "
                    "{%0,%1,%2,%3}, {%4,%5,%6,%7}, {%8,%9}, {%0,%1,%2,%3};"
                    : "+f"(acc[im][in][0]), "+f"(acc[im][in][1]),
                      "+f"(acc[im][in][2]), "+f"(acc[im][in][3])
                    : "r"(af[im][0]), "r"(af[im][1]), "r"(af[im][2]), "r"(af[im][3]),
                      "r"(bfr[in >> 1][(in & 1) * 2]), "r"(bfr[in >> 1][(in & 1) * 2 + 1]));
            }
        __syncthreads();
    }

    // epilogue: c0,c1 -> (row lq, cols 2lr,2lr+1); c2,c3 -> row lq+8
#pragma unroll
    for (int im = 0; im < 4; im++) {
#pragma unroll
        for (int half = 0; half < 2; half++) {
            int m = bm + wm + im * 16 + lq + half * 8;
            if (m >= M) continue;
#pragma unroll
            for (int in = 0; in < 4; in++) {
                int n = bn + wn + in * 8 + lr * 2;
                float o0 = acc[im][in][half * 2 + 0] + bias[n];
                float o1 = acc[im][in][half * 2 + 1] + bias[n + 1];
                if (ADD_RESID) {
                    const float2 r = *(const float2*)(R + (size_t)m * N + n);
                    o0 += r.x; o1 += r.y;
                }
                if (OUT_BF16) {
                    *(__nv_bfloat162*)((__nv_bfloat16*)Cv + (size_t)m * N + n) =
                        __floats2bfloat162_rn(o0, o1);
                } else {
                    *(float2*)((float*)Cv + (size_t)m * N + n) = make_float2(o0, o1);
                }
            }
        }
    }
}

// ---------------------------------------------------------------------------
// Deformable sampling, two-phase, 2 queries per block.
// Phase 1 (256 thr = 2 queries x 128 slots): per (head,level,point): softmax,
//   4 clamped indices + fused bilinear*attention weights -> smem.
// Phase 2: warp = head; 16 lanes x bf16x2 cover 32 channels; half-warps take
//   even/odd (level,point) slots; loop over the 2 queries.
// ---------------------------------------------------------------------------
__global__ void msda_kernel(const float* __restrict__ refp)  // [bs, nq, 4, 2]
{
    const int bq0 = blockIdx.x * 2;
    const int tid = threadIdx.x;

    __shared__ int   s_idx[2][512];
    __shared__ float s_wt[2][512];

    {
        const int q  = tid >> 7;          // query within block
        const int s  = tid & 127;         // (head, lp) slot
        const int bq = bq0 + q;
        const int l  = (s & 15) >> 2;

        // softmax over this head's 16 logits (16-lane shfl groups within warp)
        float logit = g_proj_w[(size_t)bq * 128 + s];
        float mx = logit;
#pragma unroll
        for (int o = 8; o; o >>= 1) mx = fmaxf(mx, __shfl_xor_sync(0xffffffffu, mx, o));
        float e = __expf(logit - mx);
        float ssum = e;
#pragma unroll
        for (int o = 8; o; o >>= 1) ssum += __shfl_xor_sync(0xffffffffu, ssum, o);
        const float a = e / ssum;

        const int HWs[4]    = {100, 50, 25, 13};
        const int starts[4] = {0, 10000, 12500, 13125};
        const int W = HWs[l], H = W, st = starts[l];

        const float2 off = *(const float2*)(g_proj_off + (size_t)bq * 256 + s * 2);
        const float2 ref = *(const float2*)(refp + (size_t)bq * 8 + l * 2);
        const float x = ref.x * (float)W + off.x - 0.5f;
        const float y = ref.y * (float)H + off.y - 0.5f;
        const float x0f = floorf(x), y0f = floorf(y);
        const float fx = x - x0f, fy = y - y0f;
        const int x0 = (int)x0f, y0 = (int)y0f;
        const int x1 = x0 + 1,  y1 = y0 + 1;

        const bool vx0 = (x0 >= 0) & (x0 < W), vx1 = (x1 >= 0) & (x1 < W);
        const bool vy0 = (y0 >= 0) & (y0 < H), vy1 = (y1 >= 0) & (y1 < H);
        const int cx0 = min(max(x0, 0), W - 1), cx1 = min(max(x1, 0), W - 1);
        const int cy0 = min(max(y0, 0), H - 1), cy1 = min(max(y1, 0), H - 1);

        const int base = s * 4;
        s_idx[q][base + 0] = (st + cy0 * W + cx0) * 128;
        s_idx[q][base + 1] = (st + cy0 * W + cx1) * 128;
        s_idx[q][base + 2] = (st + cy1 * W + cx0) * 128;
        s_idx[q][base + 3] = (st + cy1 * W + cx1) * 128;
        s_wt[q][base + 0] = (vx0 && vy0) ? (1.f - fx) * (1.f - fy) * a : 0.f;
        s_wt[q][base + 1] = (vx1 && vy0) ? fx * (1.f - fy) * a : 0.f;
        s_wt[q][base + 2] = (vx0 && vy1) ? (1.f - fx) * fy * a : 0.f;
        s_wt[q][base + 3] = (vx1 && vy1) ? fx * fy * a : 0.f;
    }
    __syncthreads();

    const int h    = tid >> 5, lane = tid & 31;
    const int half = lane >> 4, dd = lane & 15;

#pragma unroll
    for (int qi = 0; qi < 2; qi++) {
        const int bq = bq0 + qi;
        const int b  = bq / NQ;
        const __nv_bfloat162* vb =
            (const __nv_bfloat162*)(g_vh + (size_t)b * NV * EMBED + h * DH) + dd;

        float2 acc = make_float2(0.f, 0.f);
#pragma unroll
        for (int lp2 = 0; lp2 < 8; lp2++) {
            const int lp   = lp2 * 2 + half;
            const int base = (h * 16 + lp) * 4;
            const int4   ix = *(const int4*)&s_idx[qi][base];
            const float4 w  = *(const float4*)&s_wt[qi][base];
            float2 v0 = __bfloat1622float2(vb[ix.x]);
            float2 v1 = __bfloat1622float2(vb[ix.y]);
            float2 v2 = __bfloat1622float2(vb[ix.z]);
            float2 v3 = __bfloat1622float2(vb[ix.w]);
            acc.x += w.x * v0.x + w.y * v1.x + w.z * v2.x + w.w * v3.x;
            acc.y += w.x * v0.y + w.y * v1.y + w.z * v2.y + w.w * v3.y;
        }
        acc.x += __shfl_xor_sync(0xffffffffu, acc.x, 16);
        acc.y += __shfl_xor_sync(0xffffffffu, acc.y, 16);
        if (half == 0)
            ((float2*)(g_msda + (size_t)bq * 256 + h * DH))[dd] = acc;
    }
}

// ---------------------------------------------------------------------------
extern "C" void kernel_launch(void* const* d_in, const int* in_sizes, int n_in,
                              void* d_out, int out_size)
{
    const float* query = (const float*)d_in[0];
    const float* value = (const float*)d_in[1];
    const float* refp  = (const float*)d_in[2];
    const float* Wv    = (const float*)d_in[4];
    const float* bv    = (const float*)d_in[5];
    const float* Woff  = (const float*)d_in[6];
    const float* boff  = (const float*)d_in[7];
    const float* Ww    = (const float*)d_in[8];
    const float* bw    = (const float*)d_in[9];
    const float* Wo    = (const float*)d_in[10];
    const float* bo    = (const float*)d_in[11];
    float* out = (float*)d_out;

    void *p_vh; float *p_poff, *p_pw, *p_msda;
    cudaGetSymbolAddress(&p_vh, g_vh);
    cudaGetSymbolAddress((void**)&p_poff, g_proj_off);
    cudaGetSymbolAddress((void**)&p_pw,   g_proj_w);
    cudaGetSymbolAddress((void**)&p_msda, g_msda);

    const int Mv = BS * NV;   // 53176
    const int Mq = BS * NQ;   // 40000

    // 1) v = bf16(value @ Wv + bv)
    gemm_tc<0, 1><<<dim3(2, (Mv + 127) / 128), 256>>>(value, Wv, bv, nullptr, p_vh, Mv, 256, 256);
    // 2) offsets = query @ Woff + boff
    gemm_tc<0, 0><<<dim3(2, (Mq + 127) / 128), 256>>>(query, Woff, boff, nullptr, p_poff, Mq, 256, 256);
    // 3) logits = query @ Ww + bw
    gemm_tc<0, 0><<<dim3(1, (Mq + 127) / 128), 256>>>(query, Ww, bw, nullptr, p_pw, Mq, 128, 256);
    // 4) deformable sampling (2 queries per block)
    msda_kernel<<<Mq / 2, 256>>>(refp);
    // 5) out = msda @ Wo + bo + query
    gemm_tc<1, 0><<<dim3(2, (Mq + 127) / 128), 256>>>(p_msda, Wo, bo, query, out, Mq, 256, 256);
}

// round 10
// speedup vs baseline: 3.2212x; 1.0526x over previous
#include <cuda_runtime.h>
#include <cuda_bf16.h>
#include <math.h>
#include <stdint.h>

#define BS     4
#define NQ     10000
#define NV     13294
#define EMBED  256
#define HEADS  8
#define DH     32

// scratch (no allocations allowed)
__device__ __nv_bfloat16 g_vh[BS * HEADS * NV * DH];  // projected value, bf16, HEAD-MAJOR [b][h][pos][32]
__device__ float g_proj_off[BS * NQ * 256];
__device__ float g_proj_w[BS * NQ * 128];
__device__ float g_msda[BS * NQ * 256];

// ---------------------------------------------------------------------------
// bf16 tensor-core GEMM, double-buffered smem pipeline.
// C = A[M,K] @ B[K,N] + bias (+R). 128x128 tile, BK=16, 256 threads (8 warps
// 2x4), warp tile 64x32 = 4x4 m16n8k16 mma. ldmatrix fragment loads.
// FUSED: blocks with bn>=Nsplit switch to (B2, bias2, Cv2, N2).
// OUT_VHEAD: write bf16 head-major value layout. K multiple of 16.
// ---------------------------------------------------------------------------
template <int FUSED, int ADD_RESID, int OUT_VHEAD>
__global__ void __launch_bounds__(256, 2)
gemm_tc(const float* __restrict__ A, const float* __restrict__ Bp,
        const float* __restrict__ biasp, const float* __restrict__ R,
        void* __restrict__ Cvp, int M, int N, int K,
        const float* __restrict__ B2, const float* __restrict__ bias2,
        void* __restrict__ Cv2, int Nsplit, int N2)
{
    __shared__ __align__(16) __nv_bfloat16 As[2][128 * 24];  // [m][k], stride 24
    __shared__ __align__(16) __nv_bfloat16 Bs[2][16 * 136];  // [k][n], stride 136

    const float* B = Bp; const float* bias = biasp; void* Cv = Cvp;
    int bn = blockIdx.x * 128;
    if (FUSED && bn >= Nsplit) { B = B2; bias = bias2; Cv = Cv2; bn -= Nsplit; N = N2; }
    const int bm = blockIdx.y * 128;

    const int tid  = threadIdx.x;
    const int lane = tid & 31;
    const int wid  = tid >> 5;
    const int wm   = (wid >> 2) * 64;
    const int wn   = (wid & 3) * 32;
    const int lq   = lane >> 2, lr = lane & 3;

    const int am = tid >> 1, ak = (tid & 1) * 8;      // A: 128 rows x 16 k
    const int bk = tid >> 4, bn8 = (tid & 15) * 8;    // B: 16 rows x 128 n

    const uint32_t a_smem = (uint32_t)__cvta_generic_to_shared(&As[0][0]);
    const uint32_t b_smem = (uint32_t)__cvta_generic_to_shared(&Bs[0][0]);
    const uint32_t a_bufsz = 128 * 24 * 2;   // bytes
    const uint32_t b_bufsz = 16 * 136 * 2;

    float acc[4][4][4] = {};

    uint4 ra, rb;
    auto load_tiles = [&](int k0, uint4& rao, uint4& rbo) {
        int m = bm + am;
        float4 x, y;
        if (m < M) {
            const float4* ap = (const float4*)(A + (size_t)m * K + k0 + ak);
            x = ap[0]; y = ap[1];
        } else {
            x = make_float4(0.f, 0.f, 0.f, 0.f); y = x;
        }
        __nv_bfloat162 h0 = __floats2bfloat162_rn(x.x, x.y);
        __nv_bfloat162 h1 = __floats2bfloat162_rn(x.z, x.w);
        __nv_bfloat162 h2 = __floats2bfloat162_rn(y.x, y.y);
        __nv_bfloat162 h3 = __floats2bfloat162_rn(y.z, y.w);
        uint32_t u0, u1, u2, u3;
        memcpy(&u0, &h0, 4); memcpy(&u1, &h1, 4);
        memcpy(&u2, &h2, 4); memcpy(&u3, &h3, 4);
        rao = make_uint4(u0, u1, u2, u3);

        const float4* bp = (const float4*)(B + (size_t)(k0 + bk) * N + bn + bn8);
        float4 bx = bp[0], by = bp[1];
        h0 = __floats2bfloat162_rn(bx.x, bx.y);
        h1 = __floats2bfloat162_rn(bx.z, bx.w);
        h2 = __floats2bfloat162_rn(by.x, by.y);
        h3 = __floats2bfloat162_rn(by.z, by.w);
        memcpy(&u0, &h0, 4); memcpy(&u1, &h1, 4);
        memcpy(&u2, &h2, 4); memcpy(&u3, &h3, 4);
        rbo = make_uint4(u0, u1, u2, u3);
    };
    auto store_tiles = [&](int buf, const uint4& rai, const uint4& rbi) {
        *(uint4*)&As[buf][am * 24 + ak]  = rai;
        *(uint4*)&Bs[buf][bk * 136 + bn8] = rbi;
    };
    auto compute = [&](int buf) {
        uint32_t af[4][4], bfr[2][4];
#pragma unroll
        for (int im = 0; im < 4; im++) {
            uint32_t addr = a_smem + buf * a_bufsz +
                ((wm + im * 16 + (lane & 15)) * 24 + (lane >> 4) * 8) * 2;
            asm volatile("ldmatrix.sync.aligned.m8n8.x4.shared.b16 {%0,%1,%2,%3}, [%4];"
                         : "=r"(af[im][0]), "=r"(af[im][1]),
                           "=r"(af[im][2]), "=r"(af[im][3]) : "r"(addr));
        }
#pragma unroll
        for (int in2 = 0; in2 < 2; in2++) {
            uint32_t addr = b_smem + buf * b_bufsz +
                ((lane & 15) * 136 + wn + in2 * 16 + (lane >> 4) * 8) * 2;
            asm volatile("ldmatrix.sync.aligned.m8n8.x4.trans.shared.b16 {%0,%1,%2,%3}, [%4];"
                         : "=r"(bfr[in2][0]), "=r"(bfr[in2][1]),
                           "=r"(bfr[in2][2]), "=r"(bfr[in2][3]) : "r"(addr));
        }
#pragma unroll
        for (int im = 0; im < 4; im++)
#pragma unroll
            for (int in = 0; in < 4; in++) {
                asm volatile(
                    "mma.sync.aligned.m16n8k16.row.col.f32.bf16.bf16.f32 "
                    "{%0,%1,%2,%3}, {%4,%5,%6,%7}, {%8,%9}, {%0,%1,%2,%3};"
                    : "+f"(acc[im][in][0]), "+f"(acc[im][in][1]),
                      "+f"(acc[im][in][2]), "+f"(acc[im][in][3])
                    : "r"(af[im][0]), "r"(af[im][1]), "r"(af[im][2]), "r"(af[im][3]),
                      "r"(bfr[in >> 1][(in & 1) * 2]), "r"(bfr[in >> 1][(in & 1) * 2 + 1]));
            }
    };

    load_tiles(0, ra, rb);
    store_tiles(0, ra, rb);
    __syncthreads();
    int cur = 0;
    for (int k0 = 16; k0 < K; k0 += 16) {
        uint4 ra2, rb2;
        load_tiles(k0, ra2, rb2);     // LDG issued before compute -> overlapped
        compute(cur);
        store_tiles(cur ^ 1, ra2, rb2);
        __syncthreads();
        cur ^= 1;
    }
    compute(cur);

    // epilogue: c0,c1 -> (row lq, cols 2lr,2lr+1); c2,c3 -> row lq+8
#pragma unroll
    for (int im = 0; im < 4; im++) {
#pragma unroll
        for (int half = 0; half < 2; half++) {
            int m = bm + wm + im * 16 + lq + half * 8;
            if (m >= M) continue;
            int vb = 0, vpos = 0;
            if (OUT_VHEAD) { vb = m / NV; vpos = m - vb * NV; }
#pragma unroll
            for (int in = 0; in < 4; in++) {
                int n = bn + wn + in * 8 + lr * 2;
                float o0 = acc[im][in][half * 2 + 0] + bias[n];
                float o1 = acc[im][in][half * 2 + 1] + bias[n + 1];
                if (ADD_RESID) {
                    const float2 r = *(const float2*)(R + (size_t)m * N + n);
                    o0 += r.x; o1 += r.y;
                }
                if (OUT_VHEAD) {
                    // head-major: [b][h][pos][32], n = h*32+c
                    int hh = n >> 5, c = n & 31;
                    size_t dst = (((size_t)vb * HEADS + hh) * NV + vpos) * DH + c;
                    *(__nv_bfloat162*)((__nv_bfloat16*)Cv + dst) =
                        __floats2bfloat162_rn(o0, o1);
                } else {
                    *(float2*)((float*)Cv + (size_t)m * N + n) = make_float2(o0, o1);
                }
            }
        }
    }
}

// ---------------------------------------------------------------------------
// Deformable sampling, 2 queries/block, head-major value.
// Phase 1 (256 thr = 2q x 128 slots): per (h,l,p) -> softmax weight, 2 row-pair
//   base indices (y0,y1 rows, x-pair px..px+1) + 4 per-(half,row) weights.
// Phase 2: warp = head; 32 lanes = 2 pos-halves x 16 ch-pairs; each (h,l,p)
//   needs just 2 fully-coalesced 128B LDGs.
// ---------------------------------------------------------------------------
__global__ void msda_kernel(const float* __restrict__ refp)  // [bs, nq, 4, 2]
{
    const int bq0 = blockIdx.x * 2;
    const int tid = threadIdx.x;

    __shared__ int   s_idx[2][256];   // [q][slot*2 + row], u32-unit offsets
    __shared__ float s_wt[2][512];    // [q][slot*4 + half*2 + row]

    {
        const int q  = tid >> 7;
        const int s  = tid & 127;
        const int bq = bq0 + q;
        const int b  = bq / NQ;
        const int h  = s >> 4, lp = s & 15, l = lp >> 2;

        // softmax over this head's 16 logits (16-lane shfl groups)
        float logit = g_proj_w[(size_t)bq * 128 + s];
        float mx = logit;
#pragma unroll
        for (int o = 8; o; o >>= 1) mx = fmaxf(mx, __shfl_xor_sync(0xffffffffu, mx, o));
        float e = __expf(logit - mx);
        float ssum = e;
#pragma unroll
        for (int o = 8; o; o >>= 1) ssum += __shfl_xor_sync(0xffffffffu, ssum, o);
        const float a = e / ssum;

        const int HWs[4]    = {100, 50, 25, 13};
        const int starts[4] = {0, 10000, 12500, 13125};
        const int W = HWs[l], H = W, st = starts[l];

        const float2 off = *(const float2*)(g_proj_off + (size_t)bq * 256 + s * 2);
        const float2 ref = *(const float2*)(refp + (size_t)bq * 8 + l * 2);
        const float x = ref.x * (float)W + off.x - 0.5f;
        const float y = ref.y * (float)H + off.y - 0.5f;
        const float x0f = floorf(x), y0f = floorf(y);
        const float fx = x - x0f, fy = y - y0f;
        const int x0 = (int)x0f, y0 = (int)y0f;
        const int x1 = x0 + 1,  y1 = y0 + 1;

        const bool vx0 = (x0 >= 0) & (x0 < W), vx1 = (x1 >= 0) & (x1 < W);
        const bool vy0 = (y0 >= 0) & (y0 < H), vy1 = (y1 >= 0) & (y1 < H);
        const int cx0 = min(max(x0, 0), W - 1), cx1 = min(max(x1, 0), W - 1);
        const int cy0 = min(max(y0, 0), H - 1), cy1 = min(max(y1, 0), H - 1);
        const int px  = min(max(x0, 0), W - 2);          // x-pair base (W >= 13)
        const int s0  = cx0 - px, s1 = cx1 - px;         // 0 or 1

        const float wx0 = vx0 ? (1.f - fx) : 0.f;
        const float wx1 = vx1 ? fx : 0.f;
        const float wy0 = vy0 ? (1.f - fy) * a : 0.f;
        const float wy1 = vy1 ? fy * a : 0.f;
        const float wh0 = (s0 == 0 ? wx0 : 0.f) + (s1 == 0 ? wx1 : 0.f);
        const float wh1 = (s0 == 1 ? wx0 : 0.f) + (s1 == 1 ? wx1 : 0.f);

        const int plane = ((b * HEADS + h) * NV + st);
        s_idx[q][s * 2 + 0] = (plane + cy0 * W + px) * 16;   // row y0, u32 units
        s_idx[q][s * 2 + 1] = (plane + cy1 * W + px) * 16;   // row y1
        s_wt[q][s * 4 + 0] = wh0 * wy0;   // half0 row0
        s_wt[q][s * 4 + 1] = wh0 * wy1;   // half0 row1
        s_wt[q][s * 4 + 2] = wh1 * wy0;   // half1 row0
        s_wt[q][s * 4 + 3] = wh1 * wy1;   // half1 row1
    }
    __syncthreads();

    const int h = tid >> 5, lane = tid & 31, half = lane >> 4;
    const uint32_t* vp = (const uint32_t*)g_vh;

#pragma unroll
    for (int qi = 0; qi < 2; qi++) {
        const int bq = bq0 + qi;
        float2 acc = make_float2(0.f, 0.f);
#pragma unroll
        for (int lp = 0; lp < 16; lp++) {
            const int slot = h * 16 + lp;
            const int2   ix = *(const int2*)&s_idx[qi][slot * 2];
            const float2 w  = *(const float2*)&s_wt[qi][slot * 4 + half * 2];
            uint32_t u0 = vp[ix.x + lane];
            uint32_t u1 = vp[ix.y + lane];
            float2 v0 = __bfloat1622float2(*(const __nv_bfloat162*)&u0);
            float2 v1 = __bfloat1622float2(*(const __nv_bfloat162*)&u1);
            acc.x += w.x * v0.x + w.y * v1.x;
            acc.y += w.x * v0.y + w.y * v1.y;
        }
        acc.x += __shfl_xor_sync(0xffffffffu, acc.x, 16);
        acc.y += __shfl_xor_sync(0xffffffffu, acc.y, 16);
        if (half == 0)
            ((float2*)(g_msda + (size_t)bq * 256 + h * DH))[lane] = acc;
    }
}

// ---------------------------------------------------------------------------
extern "C" void kernel_launch(void* const* d_in, const int* in_sizes, int n_in,
                              void* d_out, int out_size)
{
    const float* query = (const float*)d_in[0];
    const float* value = (const float*)d_in[1];
    const float* refp  = (const float*)d_in[2];
    const float* Wv    = (const float*)d_in[4];
    const float* bv    = (const float*)d_in[5];
    const float* Woff  = (const float*)d_in[6];
    const float* boff  = (const float*)d_in[7];
    const float* Ww    = (const float*)d_in[8];
    const float* bw    = (const float*)d_in[9];
    const float* Wo    = (const float*)d_in[10];
    const float* bo    = (const float*)d_in[11];
    float* out = (float*)d_out;

    void *p_vh; float *p_poff, *p_pw, *p_msda;
    cudaGetSymbolAddress(&p_vh, g_vh);
    cudaGetSymbolAddress((void**)&p_poff, g_proj_off);
    cudaGetSymbolAddress((void**)&p_pw,   g_proj_w);
    cudaGetSymbolAddress((void**)&p_msda, g_msda);

    const int Mv = BS * NV;   // 53176
    const int Mq = BS * NQ;   // 40000

    // 1) v = bf16(value @ Wv + bv), head-major layout
    gemm_tc<0, 0, 1><<<dim3(2, (Mv + 127) / 128), 256>>>(
        value, Wv, bv, nullptr, p_vh, Mv, 256, 256,
        nullptr, nullptr, nullptr, 0, 0);
    // 2+3) offsets / logits fused: A=query, N = 256 | 128
    gemm_tc<1, 0, 0><<<dim3(3, (Mq + 127) / 128), 256>>>(
        query, Woff, boff, nullptr, p_poff, Mq, 256, 256,
        Ww, bw, p_pw, 256, 128);
    // 4) deformable sampling (2 queries per block)
    msda_kernel<<<Mq / 2, 256>>>(refp);
    // 5) out = msda @ Wo + bo + query
    gemm_tc<0, 1, 0><<<dim3(2, (Mq + 127) / 128), 256>>>(
        p_msda, Wo, bo, query, out, Mq, 256, 256,
        nullptr, nullptr, nullptr, 0, 0);
}

// round 11
// speedup vs baseline: 3.3271x; 1.0329x over previous
#include <cuda_runtime.h>
#include <cuda_bf16.h>
#include <math.h>
#include <stdint.h>

#define BS     4
#define NQ     10000
#define NV     13294
#define EMBED  256
#define HEADS  8
#define DH     32

typedef __nv_bfloat16 bf16;

// scratch (no allocations allowed)
__device__ bf16  g_vah[BS * NV * EMBED];          // value input, bf16
__device__ bf16  g_qh[BS * NQ * EMBED];           // query input, bf16
__device__ bf16  g_wvh[EMBED * 256];              // weights, bf16
__device__ bf16  g_woffh[EMBED * 256];
__device__ bf16  g_wwh[EMBED * 128];
__device__ bf16  g_woh[EMBED * 256];
__device__ bf16  g_vh[BS * HEADS * NV * DH];      // projected value, bf16, head-major
__device__ float g_proj_off[BS * NQ * 256];
__device__ float g_proj_w[BS * NQ * 128];
__device__ bf16  g_msdah[BS * NQ * 256];          // sampled output, bf16

// ---------------------------------------------------------------------------
// fp32 -> bf16 conversion kernels (pure bandwidth)
// ---------------------------------------------------------------------------
__device__ __forceinline__ void cvt_store4(const float4 x, bf16* d) {
    __nv_bfloat162 h0 = __floats2bfloat162_rn(x.x, x.y);
    __nv_bfloat162 h1 = __floats2bfloat162_rn(x.z, x.w);
    uint32_t u0, u1; memcpy(&u0, &h0, 4); memcpy(&u1, &h1, 4);
    *(uint2*)d = make_uint2(u0, u1);
}

__global__ void cvt2_kernel(const float* __restrict__ a, bf16* __restrict__ da, int na4,
                            const float* __restrict__ b, bf16* __restrict__ db, int nb4)
{
    int i = blockIdx.x * blockDim.x + threadIdx.x;
    int stride = gridDim.x * blockDim.x;
    for (; i < na4 + nb4; i += stride) {
        if (i < na4) cvt_store4(((const float4*)a)[i], da + i * 4);
        else {
            int j = i - na4;
            cvt_store4(((const float4*)b)[j], db + j * 4);
        }
    }
}

__global__ void cvt4_kernel(const float* __restrict__ w0, const float* __restrict__ w1,
                            const float* __restrict__ w2, const float* __restrict__ w3)
{
    const int n0 = 16384, n1 = 16384, n2 = 8192, n3 = 16384;  // float4 units
    int i = blockIdx.x * blockDim.x + threadIdx.x;
    int stride = gridDim.x * blockDim.x;
    for (; i < n0 + n1 + n2 + n3; i += stride) {
        if (i < n0)                cvt_store4(((const float4*)w0)[i], g_wvh + i * 4);
        else if (i < n0 + n1)      { int j = i - n0;           cvt_store4(((const float4*)w1)[j], g_woffh + j * 4); }
        else if (i < n0 + n1 + n2) { int j = i - n0 - n1;      cvt_store4(((const float4*)w2)[j], g_wwh + j * 4); }
        else                       { int j = i - n0 - n1 - n2; cvt_store4(((const float4*)w3)[j], g_woh + j * 4); }
    }
}

// ---------------------------------------------------------------------------
// bf16 tensor-core GEMM, cp.async 3-stage pipeline, runtime descriptors.
// 128x128 tile, BK=16, K=256 fixed, 256 threads (8 warps 2x4),
// warp tile 64x32 = 4x4 m16n8k16 mma. ldmatrix fragment loads.
// mode: 0 = fp32 out, 1 = head-major bf16 value out, 2 = fp32 out + residual.
// ---------------------------------------------------------------------------
struct GemmDesc {
    const bf16* A; const bf16* B; const float* bias; const float* R;
    void* C; int M, N, mblk, nblk, mode;
};

#define GK      256
#define NKIT    16
#define NSTAGE  3
#define A_STRIDE 24      // halves per A smem row
#define B_STRIDE 136     // halves per B smem row
#define A_STAGE (128 * A_STRIDE)   // halves
#define B_STAGE (16 * B_STRIDE)

__device__ __forceinline__ void cp_async16(uint32_t dst, const void* src, bool full) {
    int sz = full ? 16 : 0;
    asm volatile("cp.async.ca.shared.global [%0], [%1], 16, %2;"
                 :: "r"(dst), "l"(src), "r"(sz));
}

__global__ void __launch_bounds__(256, 2)
gemm_mega(GemmDesc d0, GemmDesc d1, GemmDesc d2)
{
    __shared__ __align__(16) bf16 As[NSTAGE][A_STAGE];
    __shared__ __align__(16) bf16 Bs[NSTAGE][B_STAGE];

    GemmDesc d = d0;
    int bid = blockIdx.x;
    if (bid >= d0.mblk * d0.nblk) {
        bid -= d0.mblk * d0.nblk;
        if (bid < d1.mblk * d1.nblk) d = d1;
        else { bid -= d1.mblk * d1.nblk; d = d2; }
    }
    const int bm = (bid / d.nblk) * 128;
    const int bn = (bid % d.nblk) * 128;

    const int tid  = threadIdx.x;
    const int lane = tid & 31;
    const int wid  = tid >> 5;
    const int wm   = (wid >> 2) * 64;
    const int wn   = (wid & 3) * 32;
    const int lq   = lane >> 2, lr = lane & 3;

    const int am = tid >> 1, ak = (tid & 1) * 8;      // A copy: 2 thr/row
    const int bk = tid >> 4, bn8 = (tid & 15) * 8;    // B copy: 16 thr/row

    const uint32_t a_smem = (uint32_t)__cvta_generic_to_shared(&As[0][0]);
    const uint32_t b_smem = (uint32_t)__cvta_generic_to_shared(&Bs[0][0]);

    const bool a_ok  = (bm + am) < d.M;
    const int  a_row = a_ok ? (bm + am) : 0;
    const bf16* a_src = d.A + (size_t)a_row * GK + ak;
    const bf16* b_src = d.B + (size_t)bk * d.N + bn + bn8;
    const uint32_t a_dst = a_smem + (am * A_STRIDE + ak) * 2;
    const uint32_t b_dst = b_smem + (bk * B_STRIDE + bn8) * 2;

    auto issue_copy = [&](int s, int k0) {
        cp_async16(a_dst + s * A_STAGE * 2, a_src + k0, a_ok);
        cp_async16(b_dst + s * B_STAGE * 2, b_src + (size_t)k0 * d.N, true);
        asm volatile("cp.async.commit_group;");
    };

    float acc[4][4][4] = {};

#pragma unroll
    for (int s = 0; s < NSTAGE - 1; s++) issue_copy(s, s * 16);

    int buf = 0;
#pragma unroll 4
    for (int i = 0; i < NKIT; i++) {
        asm volatile("cp.async.wait_group %0;" :: "n"(NSTAGE - 2));
        __syncthreads();

        const int pf = i + NSTAGE - 1;
        if (pf < NKIT) issue_copy(pf % NSTAGE, pf * 16);
        else asm volatile("cp.async.commit_group;");

        // compute tile buf
        uint32_t af[4][4], bfr[2][4];
#pragma unroll
        for (int im = 0; im < 4; im++) {
            uint32_t addr = a_smem + buf * A_STAGE * 2 +
                ((wm + im * 16 + (lane & 15)) * A_STRIDE + (lane >> 4) * 8) * 2;
            asm volatile("ldmatrix.sync.aligned.m8n8.x4.shared.b16 {%0,%1,%2,%3}, [%4];"
                         : "=r"(af[im][0]), "=r"(af[im][1]),
                           "=r"(af[im][2]), "=r"(af[im][3]) : "r"(addr));
        }
#pragma unroll
        for (int in2 = 0; in2 < 2; in2++) {
            uint32_t addr = b_smem + buf * B_STAGE * 2 +
                ((lane & 15) * B_STRIDE + wn + in2 * 16 + (lane >> 4) * 8) * 2;
            asm volatile("ldmatrix.sync.aligned.m8n8.x4.trans.shared.b16 {%0,%1,%2,%3}, [%4];"
                         : "=r"(bfr[in2][0]), "=r"(bfr[in2][1]),
                           "=r"(bfr[in2][2]), "=r"(bfr[in2][3]) : "r"(addr));
        }
#pragma unroll
        for (int im = 0; im < 4; im++)
#pragma unroll
            for (int in = 0; in < 4; in++) {
                asm volatile(
                    "mma.sync.aligned.m16n8k16.row.col.f32.bf16.bf16.f32 "
                    "{%0,%1,%2,%3}, {%4,%5,%6,%7}, {%8,%9}, {%0,%1,%2,%3};"
                    : "+f"(acc[im][in][0]), "+f"(acc[im][in][1]),
                      "+f"(acc[im][in][2]), "+f"(acc[im][in][3])
                    : "r"(af[im][0]), "r"(af[im][1]), "r"(af[im][2]), "r"(af[im][3]),
                      "r"(bfr[in >> 1][(in & 1) * 2]), "r"(bfr[in >> 1][(in & 1) * 2 + 1]));
            }
        buf = (buf + 1 == NSTAGE) ? 0 : buf + 1;
    }

    // epilogue
#pragma unroll
    for (int im = 0; im < 4; im++) {
#pragma unroll
        for (int half = 0; half < 2; half++) {
            int m = bm + wm + im * 16 + lq + half * 8;
            if (m >= d.M) continue;
            int vb = m / NV, vpos = m - vb * NV;   // only used for mode 1
#pragma unroll
            for (int in = 0; in < 4; in++) {
                int n = bn + wn + in * 8 + lr * 2;
                float o0 = acc[im][in][half * 2 + 0] + d.bias[n];
                float o1 = acc[im][in][half * 2 + 1] + d.bias[n + 1];
                if (d.mode == 2) {
                    const float2 r = *(const float2*)(d.R + (size_t)m * d.N + n);
                    o0 += r.x; o1 += r.y;
                }
                if (d.mode == 1) {
                    int hh = n >> 5, c = n & 31;
                    size_t dst = (((size_t)vb * HEADS + hh) * NV + vpos) * DH + c;
                    *(__nv_bfloat162*)((bf16*)d.C + dst) = __floats2bfloat162_rn(o0, o1);
                } else {
                    *(float2*)((float*)d.C + (size_t)m * d.N + n) = make_float2(o0, o1);
                }
            }
        }
    }
}

// ---------------------------------------------------------------------------
// Deformable sampling, 2 queries/block, head-major value, bf16 output.
// Phase 1: per (h,l,p): softmax weight + 2 row-pair indices + per-half weights,
//   packed as two 16B records [idx0, idx1, w_r0, w_r1] (one per half).
// Phase 2: warp = head; 32 lanes = 2 pos x 16 ch-pairs; per (h,l,p):
//   1 LDS.128 + 2 coalesced 128B LDGs.
// ---------------------------------------------------------------------------
__global__ void msda_kernel(const float* __restrict__ refp)  // [bs, nq, 4, 2]
{
    const int bq0 = blockIdx.x * 2;
    const int tid = threadIdx.x;

    __shared__ int4 s_rec[2][256];   // [q][slot*2 + half] = {idx0, idx1, w0, w1}

    {
        const int q  = tid >> 7;
        const int s  = tid & 127;
        const int bq = bq0 + q;
        const int b  = bq / NQ;
        const int h  = s >> 4, lp = s & 15, l = lp >> 2;

        float logit = g_proj_w[(size_t)bq * 128 + s];
        float mx = logit;
#pragma unroll
        for (int o = 8; o; o >>= 1) mx = fmaxf(mx, __shfl_xor_sync(0xffffffffu, mx, o));
        float e = __expf(logit - mx);
        float ssum = e;
#pragma unroll
        for (int o = 8; o; o >>= 1) ssum += __shfl_xor_sync(0xffffffffu, ssum, o);
        const float a = e / ssum;

        const int HWs[4]    = {100, 50, 25, 13};
        const int starts[4] = {0, 10000, 12500, 13125};
        const int W = HWs[l], H = W, st = starts[l];

        const float2 off = *(const float2*)(g_proj_off + (size_t)bq * 256 + s * 2);
        const float2 ref = *(const float2*)(refp + (size_t)bq * 8 + l * 2);
        const float x = ref.x * (float)W + off.x - 0.5f;
        const float y = ref.y * (float)H + off.y - 0.5f;
        const float x0f = floorf(x), y0f = floorf(y);
        const float fx = x - x0f, fy = y - y0f;
        const int x0 = (int)x0f, y0 = (int)y0f;
        const int x1 = x0 + 1,  y1 = y0 + 1;

        const bool vx0 = (x0 >= 0) & (x0 < W), vx1 = (x1 >= 0) & (x1 < W);
        const bool vy0 = (y0 >= 0) & (y0 < H), vy1 = (y1 >= 0) & (y1 < H);
        const int cx0 = min(max(x0, 0), W - 1), cx1 = min(max(x1, 0), W - 1);
        const int cy0 = min(max(y0, 0), H - 1), cy1 = min(max(y1, 0), H - 1);
        const int px  = min(max(x0, 0), W - 2);
        const int s0  = cx0 - px, s1 = cx1 - px;

        const float wx0 = vx0 ? (1.f - fx) : 0.f;
        const float wx1 = vx1 ? fx : 0.f;
        const float wy0 = vy0 ? (1.f - fy) * a : 0.f;
        const float wy1 = vy1 ? fy * a : 0.f;
        const float wh0 = (s0 == 0 ? wx0 : 0.f) + (s1 == 0 ? wx1 : 0.f);
        const float wh1 = (s0 == 1 ? wx0 : 0.f) + (s1 == 1 ? wx1 : 0.f);

        const int plane = ((b * HEADS + h) * NV + st);
        const int i0 = (plane + cy0 * W + px) * 16;   // u32 units
        const int i1 = (plane + cy1 * W + px) * 16;
        s_rec[q][s * 2 + 0] = make_int4(i0, i1, __float_as_int(wh0 * wy0),
                                                __float_as_int(wh0 * wy1));
        s_rec[q][s * 2 + 1] = make_int4(i0, i1, __float_as_int(wh1 * wy0),
                                                __float_as_int(wh1 * wy1));
    }
    __syncthreads();

    const int h = tid >> 5, lane = tid & 31, half = lane >> 4;
    const uint32_t* vp = (const uint32_t*)g_vh;

#pragma unroll
    for (int qi = 0; qi < 2; qi++) {
        const int bq = bq0 + qi;
        float2 acc = make_float2(0.f, 0.f);
#pragma unroll
        for (int lp = 0; lp < 16; lp++) {
            const int4 rec = s_rec[qi][(h * 16 + lp) * 2 + half];
            const float w0 = __int_as_float(rec.z), w1 = __int_as_float(rec.w);
            uint32_t u0 = vp[rec.x + lane];
            uint32_t u1 = vp[rec.y + lane];
            float2 v0 = __bfloat1622float2(*(const __nv_bfloat162*)&u0);
            float2 v1 = __bfloat1622float2(*(const __nv_bfloat162*)&u1);
            acc.x += w0 * v0.x + w1 * v1.x;
            acc.y += w0 * v0.y + w1 * v1.y;
        }
        acc.x += __shfl_xor_sync(0xffffffffu, acc.x, 16);
        acc.y += __shfl_xor_sync(0xffffffffu, acc.y, 16);
        if (half == 0) {
            __nv_bfloat162 hv = __floats2bfloat162_rn(acc.x, acc.y);
            uint32_t uv; memcpy(&uv, &hv, 4);
            ((uint32_t*)g_msdah)[(size_t)bq * 128 + h * 16 + lane] = uv;
        }
    }
}

// ---------------------------------------------------------------------------
extern "C" void kernel_launch(void* const* d_in, const int* in_sizes, int n_in,
                              void* d_out, int out_size)
{
    const float* query = (const float*)d_in[0];
    const float* value = (const float*)d_in[1];
    const float* refp  = (const float*)d_in[2];
    const float* Wv    = (const float*)d_in[4];
    const float* bv    = (const float*)d_in[5];
    const float* Woff  = (const float*)d_in[6];
    const float* boff  = (const float*)d_in[7];
    const float* Ww    = (const float*)d_in[8];
    const float* bw    = (const float*)d_in[9];
    const float* Wo    = (const float*)d_in[10];
    const float* bo    = (const float*)d_in[11];
    float* out = (float*)d_out;

    bf16 *p_vah, *p_qh, *p_wvh, *p_woffh, *p_wwh, *p_woh, *p_vh, *p_msdah;
    float *p_poff, *p_pw;
    cudaGetSymbolAddress((void**)&p_vah,   g_vah);
    cudaGetSymbolAddress((void**)&p_qh,    g_qh);
    cudaGetSymbolAddress((void**)&p_wvh,   g_wvh);
    cudaGetSymbolAddress((void**)&p_woffh, g_woffh);
    cudaGetSymbolAddress((void**)&p_wwh,   g_wwh);
    cudaGetSymbolAddress((void**)&p_woh,   g_woh);
    cudaGetSymbolAddress((void**)&p_vh,    g_vh);
    cudaGetSymbolAddress((void**)&p_poff,  g_proj_off);
    cudaGetSymbolAddress((void**)&p_pw,    g_proj_w);
    cudaGetSymbolAddress((void**)&p_msdah, g_msdah);

    const int Mv = BS * NV;   // 53176
    const int Mq = BS * NQ;   // 40000

    // 0) fp32 -> bf16 conversions
    cvt2_kernel<<<1024, 256>>>(query, p_qh, Mq * 256 / 4, value, p_vah, Mv * 256 / 4);
    cvt4_kernel<<<112, 256>>>(Wv, Woff, Ww, Wo);

    // 1-3) fused: value proj (head-major bf16) + offsets + logits
    GemmDesc dv   = {p_vah, p_wvh,   bv,   nullptr, p_vh,   Mv, 256, (Mv + 127) / 128, 2, 1};
    GemmDesc doff = {p_qh,  p_woffh, boff, nullptr, p_poff, Mq, 256, (Mq + 127) / 128, 2, 0};
    GemmDesc dw   = {p_qh,  p_wwh,   bw,   nullptr, p_pw,   Mq, 128, (Mq + 127) / 128, 1, 0};
    int nblocks = dv.mblk * dv.nblk + doff.mblk * doff.nblk + dw.mblk * dw.nblk;
    gemm_mega<<<nblocks, 256>>>(dv, doff, dw);

    // 4) deformable sampling
    msda_kernel<<<Mq / 2, 256>>>(refp);

    // 5) out = msda @ Wo + bo + query
    GemmDesc dout = {p_msdah, p_woh, bo, query, out, Mq, 256, (Mq + 127) / 128, 2, 2};
    GemmDesc dnull = {nullptr, nullptr, nullptr, nullptr, nullptr, 0, 0, 0, 0, 0};
    gemm_mega<<<dout.mblk * dout.nblk, 256>>>(dout, dnull, dnull);
}

// round 12
// speedup vs baseline: 3.8893x; 1.1690x over previous
#include <cuda_runtime.h>
#include <cuda_bf16.h>
#include <math.h>
#include <stdint.h>

#define BS     4
#define NQ     10000
#define NV     13294
#define EMBED  256
#define HEADS  8
#define DH     32

typedef __nv_bfloat16 bf16;

// scratch (no allocations allowed)
__device__ bf16  g_vah[BS * NV * EMBED];          // value input, bf16
__device__ bf16  g_qh[BS * NQ * EMBED];           // query input, bf16
__device__ bf16  g_wvh[EMBED * 256];              // weights, bf16
__device__ bf16  g_woffh[EMBED * 256];
__device__ bf16  g_wwh[EMBED * 128];
__device__ bf16  g_woh[EMBED * 256];
__device__ bf16  g_vh[BS * HEADS * NV * DH];      // projected value, bf16, head-major
__device__ float g_proj_off[BS * NQ * 256];
__device__ float g_proj_w[BS * NQ * 128];
__device__ bf16  g_msdah[BS * NQ * 256];          // sampled output, bf16

// ---------------------------------------------------------------------------
// fp32 -> bf16 conversion, all 6 tensors in one launch (pure bandwidth)
// ---------------------------------------------------------------------------
__device__ __forceinline__ void cvt_store4(const float4 x, bf16* d) {
    __nv_bfloat162 h0 = __floats2bfloat162_rn(x.x, x.y);
    __nv_bfloat162 h1 = __floats2bfloat162_rn(x.z, x.w);
    uint32_t u0, u1; memcpy(&u0, &h0, 4); memcpy(&u1, &h1, 4);
    *(uint2*)d = make_uint2(u0, u1);
}

#define NQ4 (BS * NQ * EMBED / 4)   // 2,560,000
#define NV4 (BS * NV * EMBED / 4)   // 850,816... (13294*4*256/4 = 3,403,264/4? no)
// careful: BS*NV*EMBED/4 = 4*13294*256/4 = 3,403,264 / 4 -> compute in code

__global__ void cvt_all_kernel(const float* __restrict__ q, const float* __restrict__ v,
                               const float* __restrict__ w0, const float* __restrict__ w1,
                               const float* __restrict__ w2, const float* __restrict__ w3)
{
    const int nq = BS * NQ * EMBED / 4;   // 2,560,000
    const int nv = BS * NV * EMBED / 4;   // 850,816 * 4 /4 ... = 3,403,264/4
    const int n0 = 16384, n1 = 16384, n2 = 8192, n3 = 16384;
    const int total = nq + nv + n0 + n1 + n2 + n3;
    int i = blockIdx.x * blockDim.x + threadIdx.x;
    int stride = gridDim.x * blockDim.x;
    for (; i < total; i += stride) {
        int j = i;
        if (j < nq) { cvt_store4(((const float4*)q)[j], g_qh + j * 4); continue; }
        j -= nq;
        if (j < nv) { cvt_store4(((const float4*)v)[j], g_vah + j * 4); continue; }
        j -= nv;
        if (j < n0) { cvt_store4(((const float4*)w0)[j], g_wvh + j * 4); continue; }
        j -= n0;
        if (j < n1) { cvt_store4(((const float4*)w1)[j], g_woffh + j * 4); continue; }
        j -= n1;
        if (j < n2) { cvt_store4(((const float4*)w2)[j], g_wwh + j * 4); continue; }
        j -= n2;
        cvt_store4(((const float4*)w3)[j], g_woh + j * 4);
    }
}

// ---------------------------------------------------------------------------
// bf16 tensor-core GEMM, cp.async 4-stage pipeline, runtime descriptors.
// 128x128 tile, BK=16, K=256 fixed, 256 threads (8 warps 2x4),
// warp tile 64x32 = 4x4 m16n8k16 mma. ldmatrix fragment loads.
// mode: 0 = fp32 out, 1 = head-major bf16 value out, 2 = fp32 out + residual.
// ---------------------------------------------------------------------------
struct GemmDesc {
    const bf16* A; const bf16* B; const float* bias; const float* R;
    void* C; int M, N, mblk, nblk, mode;
};

#define GK      256
#define NKIT    16
#define NSTAGE  4
#define A_STRIDE 24      // halves per A smem row
#define B_STRIDE 136     // halves per B smem row
#define A_STAGE (128 * A_STRIDE)   // halves
#define B_STAGE (16 * B_STRIDE)

__device__ __forceinline__ void cp_async16(uint32_t dst, const void* src, bool full) {
    int sz = full ? 16 : 0;
    asm volatile("cp.async.ca.shared.global [%0], [%1], 16, %2;"
                 :: "r"(dst), "l"(src), "r"(sz));
}

__global__ void __launch_bounds__(256, 2)
gemm_mega(GemmDesc d0, GemmDesc d1, GemmDesc d2)
{
    __shared__ __align__(16) bf16 As[NSTAGE][A_STAGE];
    __shared__ __align__(16) bf16 Bs[NSTAGE][B_STAGE];

    GemmDesc d = d0;
    int bid = blockIdx.x;
    if (bid >= d0.mblk * d0.nblk) {
        bid -= d0.mblk * d0.nblk;
        if (bid < d1.mblk * d1.nblk) d = d1;
        else { bid -= d1.mblk * d1.nblk; d = d2; }
    }
    const int bm = (bid / d.nblk) * 128;
    const int bn = (bid % d.nblk) * 128;

    const int tid  = threadIdx.x;
    const int lane = tid & 31;
    const int wid  = tid >> 5;
    const int wm   = (wid >> 2) * 64;
    const int wn   = (wid & 3) * 32;
    const int lq   = lane >> 2, lr = lane & 3;

    const int am = tid >> 1, ak = (tid & 1) * 8;      // A copy: 2 thr/row
    const int bk = tid >> 4, bn8 = (tid & 15) * 8;    // B copy: 16 thr/row

    const uint32_t a_smem = (uint32_t)__cvta_generic_to_shared(&As[0][0]);
    const uint32_t b_smem = (uint32_t)__cvta_generic_to_shared(&Bs[0][0]);

    const bool a_ok  = (bm + am) < d.M;
    const int  a_row = a_ok ? (bm + am) : 0;
    const bf16* a_src = d.A + (size_t)a_row * GK + ak;
    const bf16* b_src = d.B + (size_t)bk * d.N + bn + bn8;
    const uint32_t a_dst = a_smem + (am * A_STRIDE + ak) * 2;
    const uint32_t b_dst = b_smem + (bk * B_STRIDE + bn8) * 2;

    auto issue_copy = [&](int s, int k0) {
        cp_async16(a_dst + s * A_STAGE * 2, a_src + k0, a_ok);
        cp_async16(b_dst + s * B_STAGE * 2, b_src + (size_t)k0 * d.N, true);
        asm volatile("cp.async.commit_group;");
    };

    float acc[4][4][4] = {};

#pragma unroll
    for (int s = 0; s < NSTAGE - 1; s++) issue_copy(s, s * 16);

#pragma unroll
    for (int i = 0; i < NKIT; i++) {
        asm volatile("cp.async.wait_group %0;" :: "n"(NSTAGE - 2));
        __syncthreads();

        const int pf = i + NSTAGE - 1;
        if (pf < NKIT) issue_copy(pf & (NSTAGE - 1), pf * 16);
        else asm volatile("cp.async.commit_group;");

        const int buf = i & (NSTAGE - 1);
        uint32_t af[4][4], bfr[2][4];
#pragma unroll
        for (int im = 0; im < 4; im++) {
            uint32_t addr = a_smem + buf * A_STAGE * 2 +
                ((wm + im * 16 + (lane & 15)) * A_STRIDE + (lane >> 4) * 8) * 2;
            asm volatile("ldmatrix.sync.aligned.m8n8.x4.shared.b16 {%0,%1,%2,%3}, [%4];"
                         : "=r"(af[im][0]), "=r"(af[im][1]),
                           "=r"(af[im][2]), "=r"(af[im][3]) : "r"(addr));
        }
#pragma unroll
        for (int in2 = 0; in2 < 2; in2++) {
            uint32_t addr = b_smem + buf * B_STAGE * 2 +
                ((lane & 15) * B_STRIDE + wn + in2 * 16 + (lane >> 4) * 8) * 2;
            asm volatile("ldmatrix.sync.aligned.m8n8.x4.trans.shared.b16 {%0,%1,%2,%3}, [%4];"
                         : "=r"(bfr[in2][0]), "=r"(bfr[in2][1]),
                           "=r"(bfr[in2][2]), "=r"(bfr[in2][3]) : "r"(addr));
        }
#pragma unroll
        for (int im = 0; im < 4; im++)
#pragma unroll
            for (int in = 0; in < 4; in++) {
                asm volatile(
                    "mma.sync.aligned.m16n8k16.row.col.f32.bf16.bf16.f32 "
                    "{%0,%1,%2,%3}, {%4,%5,%6,%7}, {%8,%9}, {%0,%1,%2,%3};"
                    : "+f"(acc[im][in][0]), "+f"(acc[im][in][1]),
                      "+f"(acc[im][in][2]), "+f"(acc[im][in][3])
                    : "r"(af[im][0]), "r"(af[im][1]), "r"(af[im][2]), "r"(af[im][3]),
                      "r"(bfr[in >> 1][(in & 1) * 2]), "r"(bfr[in >> 1][(in & 1) * 2 + 1]));
            }
    }

    // epilogue
#pragma unroll
    for (int im = 0; im < 4; im++) {
#pragma unroll
        for (int half = 0; half < 2; half++) {
            int m = bm + wm + im * 16 + lq + half * 8;
            if (m >= d.M) continue;
            int vb = m / NV, vpos = m - vb * NV;   // only used for mode 1
#pragma unroll
            for (int in = 0; in < 4; in++) {
                int n = bn + wn + in * 8 + lr * 2;
                float o0 = acc[im][in][half * 2 + 0] + d.bias[n];
                float o1 = acc[im][in][half * 2 + 1] + d.bias[n + 1];
                if (d.mode == 2) {
                    const float2 r = *(const float2*)(d.R + (size_t)m * d.N + n);
                    o0 += r.x; o1 += r.y;
                }
                if (d.mode == 1) {
                    int hh = n >> 5, c = n & 31;
                    size_t dst = (((size_t)vb * HEADS + hh) * NV + vpos) * DH + c;
                    *(__nv_bfloat162*)((bf16*)d.C + dst) = __floats2bfloat162_rn(o0, o1);
                } else {
                    *(float2*)((float*)d.C + (size_t)m * d.N + n) = make_float2(o0, o1);
                }
            }
        }
    }
}

// ---------------------------------------------------------------------------
// Deformable sampling, 2 queries/block, head-major value, bf16 output.
// Phase 1: per (h,l,p) slot: softmax weight + x-pair row bases; writes 4
//   packed records {row_base_u32, weight} for (pos,row) in {0,1}^2.
// Phase 2: warp = head; lane owns one (row=lane>>4, pos=(lane>>3)&1,
//   chquad=lane&7) -> per slot: 1 LDS.64 + 1 LDG.64 + 4 FFMA. Corner
//   reduction deferred to 2 shfl-xor stages per query.
// ---------------------------------------------------------------------------
__global__ void msda_kernel(const float* __restrict__ refp)  // [bs, nq, 4, 2]
{
    const int bq0 = blockIdx.x * 2;
    const int tid = threadIdx.x;

    __shared__ uint2 s_rec[2][512];   // [q][slot*4 + pos*2 + row] = {rowbase_u32, w}

    {
        const int q  = tid >> 7;
        const int s  = tid & 127;
        const int bq = bq0 + q;
        const int b  = bq / NQ;
        const int h  = s >> 4, lp = s & 15, l = lp >> 2;

        float logit = g_proj_w[(size_t)bq * 128 + s];
        float mx = logit;
#pragma unroll
        for (int o = 8; o; o >>= 1) mx = fmaxf(mx, __shfl_xor_sync(0xffffffffu, mx, o));
        float e = __expf(logit - mx);
        float ssum = e;
#pragma unroll
        for (int o = 8; o; o >>= 1) ssum += __shfl_xor_sync(0xffffffffu, ssum, o);
        const float a = e / ssum;

        const int HWs[4]    = {100, 50, 25, 13};
        const int starts[4] = {0, 10000, 12500, 13125};
        const int W = HWs[l], H = W, st = starts[l];

        const float2 off = *(const float2*)(g_proj_off + (size_t)bq * 256 + s * 2);
        const float2 ref = *(const float2*)(refp + (size_t)bq * 8 + l * 2);
        const float x = ref.x * (float)W + off.x - 0.5f;
        const float y = ref.y * (float)H + off.y - 0.5f;
        const float x0f = floorf(x), y0f = floorf(y);
        const float fx = x - x0f, fy = y - y0f;
        const int x0 = (int)x0f, y0 = (int)y0f;
        const int x1 = x0 + 1,  y1 = y0 + 1;

        const bool vx0 = (x0 >= 0) & (x0 < W), vx1 = (x1 >= 0) & (x1 < W);
        const bool vy0 = (y0 >= 0) & (y0 < H), vy1 = (y1 >= 0) & (y1 < H);
        const int cx0 = min(max(x0, 0), W - 1), cx1 = min(max(x1, 0), W - 1);
        const int cy0 = min(max(y0, 0), H - 1), cy1 = min(max(y1, 0), H - 1);
        const int px  = min(max(x0, 0), W - 2);
        const int s0  = cx0 - px, s1 = cx1 - px;

        const float wx0 = vx0 ? (1.f - fx) : 0.f;
        const float wx1 = vx1 ? fx : 0.f;
        const float wy0 = vy0 ? (1.f - fy) * a : 0.f;
        const float wy1 = vy1 ? fy * a : 0.f;
        const float wh0 = (s0 == 0 ? wx0 : 0.f) + (s1 == 0 ? wx1 : 0.f);  // pos 0 (px)
        const float wh1 = (s0 == 1 ? wx0 : 0.f) + (s1 == 1 ? wx1 : 0.f);  // pos 1 (px+1)

        const int plane = ((b * HEADS + h) * NV + st);
        const uint32_t i0 = (uint32_t)(plane + cy0 * W + px) * 16u;   // u32 units
        const uint32_t i1 = (uint32_t)(plane + cy1 * W + px) * 16u;
        const int base = s * 4;
        s_rec[q][base + 0] = make_uint2(i0, (uint32_t)__float_as_int(wh0 * wy0)); // pos0,row0
        s_rec[q][base + 1] = make_uint2(i1, (uint32_t)__float_as_int(wh0 * wy1)); // pos0,row1
        s_rec[q][base + 2] = make_uint2(i0, (uint32_t)__float_as_int(wh1 * wy0)); // pos1,row0
        s_rec[q][base + 3] = make_uint2(i1, (uint32_t)__float_as_int(wh1 * wy1)); // pos1,row1
    }
    __syncthreads();

    const int h    = tid >> 5, lane = tid & 31;
    const int row  = lane >> 4;          // 0/1
    const int pos  = (lane >> 3) & 1;    // 0/1
    const int cq   = lane & 7;           // channel quad
    const int laneoff = pos * 16 + cq * 2;   // u32 offset within row-pair
    const int recsel  = pos * 2 + row;
    const uint32_t* vp = (const uint32_t*)g_vh;

#pragma unroll
    for (int qi = 0; qi < 2; qi++) {
        const int bq = bq0 + qi;
        float a0 = 0.f, a1 = 0.f, a2 = 0.f, a3 = 0.f;
#pragma unroll
        for (int lp = 0; lp < 16; lp++) {
            const uint2 rec = s_rec[qi][(h * 16 + lp) * 4 + recsel];
            const float w = __int_as_float((int)rec.y);
            const uint2 dv = *(const uint2*)(vp + rec.x + laneoff);
            float2 v0 = __bfloat1622float2(*(const __nv_bfloat162*)&dv.x);
            float2 v1 = __bfloat1622float2(*(const __nv_bfloat162*)&dv.y);
            a0 += w * v0.x; a1 += w * v0.y;
            a2 += w * v1.x; a3 += w * v1.y;
        }
        // reduce over pos (xor 8) and row (xor 16)
        a0 += __shfl_xor_sync(0xffffffffu, a0, 8);
        a1 += __shfl_xor_sync(0xffffffffu, a1, 8);
        a2 += __shfl_xor_sync(0xffffffffu, a2, 8);
        a3 += __shfl_xor_sync(0xffffffffu, a3, 8);
        a0 += __shfl_xor_sync(0xffffffffu, a0, 16);
        a1 += __shfl_xor_sync(0xffffffffu, a1, 16);
        a2 += __shfl_xor_sync(0xffffffffu, a2, 16);
        a3 += __shfl_xor_sync(0xffffffffu, a3, 16);
        if (lane < 8) {
            __nv_bfloat162 p0 = __floats2bfloat162_rn(a0, a1);
            __nv_bfloat162 p1 = __floats2bfloat162_rn(a2, a3);
            uint32_t u0, u1; memcpy(&u0, &p0, 4); memcpy(&u1, &p1, 4);
            ((uint2*)g_msdah)[(size_t)bq * 64 + h * 8 + cq] = make_uint2(u0, u1);
        }
    }
}

// ---------------------------------------------------------------------------
extern "C" void kernel_launch(void* const* d_in, const int* in_sizes, int n_in,
                              void* d_out, int out_size)
{
    const float* query = (const float*)d_in[0];
    const float* value = (const float*)d_in[1];
    const float* refp  = (const float*)d_in[2];
    const float* Wv    = (const float*)d_in[4];
    const float* bv    = (const float*)d_in[5];
    const float* Woff  = (const float*)d_in[6];
    const float* boff  = (const float*)d_in[7];
    const float* Ww    = (const float*)d_in[8];
    const float* bw    = (const float*)d_in[9];
    const float* Wo    = (const float*)d_in[10];
    const float* bo    = (const float*)d_in[11];
    float* out = (float*)d_out;

    bf16 *p_vah, *p_qh, *p_wvh, *p_woffh, *p_wwh, *p_woh, *p_vh, *p_msdah;
    float *p_poff, *p_pw;
    cudaGetSymbolAddress((void**)&p_vah,   g_vah);
    cudaGetSymbolAddress((void**)&p_qh,    g_qh);
    cudaGetSymbolAddress((void**)&p_wvh,   g_wvh);
    cudaGetSymbolAddress((void**)&p_woffh, g_woffh);
    cudaGetSymbolAddress((void**)&p_wwh,   g_wwh);
    cudaGetSymbolAddress((void**)&p_woh,   g_woh);
    cudaGetSymbolAddress((void**)&p_vh,    g_vh);
    cudaGetSymbolAddress((void**)&p_poff,  g_proj_off);
    cudaGetSymbolAddress((void**)&p_pw,    g_proj_w);
    cudaGetSymbolAddress((void**)&p_msdah, g_msdah);

    const int Mv = BS * NV;   // 53176
    const int Mq = BS * NQ;   // 40000

    // 0) fp32 -> bf16 conversions (one launch)
    cvt_all_kernel<<<1184, 256>>>(query, value, Wv, Woff, Ww, Wo);

    // 1-3) fused: value proj (head-major bf16) + offsets + logits
    GemmDesc dv   = {p_vah, p_wvh,   bv,   nullptr, p_vh,   Mv, 256, (Mv + 127) / 128, 2, 1};
    GemmDesc doff = {p_qh,  p_woffh, boff, nullptr, p_poff, Mq, 256, (Mq + 127) / 128, 2, 0};
    GemmDesc dw   = {p_qh,  p_wwh,   bw,   nullptr, p_pw,   Mq, 128, (Mq + 127) / 128, 1, 0};
    int nblocks = dv.mblk * dv.nblk + doff.mblk * doff.nblk + dw.mblk * dw.nblk;
    gemm_mega<<<nblocks, 256>>>(dv, doff, dw);

    // 4) deformable sampling
    msda_kernel<<<Mq / 2, 256>>>(refp);

    // 5) out = msda @ Wo + bo + query
    GemmDesc dout = {p_msdah, p_woh, bo, query, out, Mq, 256, (Mq + 127) / 128, 2, 2};
    GemmDesc dnull = {nullptr, nullptr, nullptr, nullptr, nullptr, 0, 0, 0, 0, 0};
    gemm_mega<<<dout.mblk * dout.nblk, 256>>>(dout, dnull, dnull);
}